// round 1
// baseline (speedup 1.0000x reference)
#include <cuda_runtime.h>
#include <cuda_bf16.h>
#include <math.h>
#include <stdint.h>

#define BB 64
#define LL 256
#define EE 512
#define HH 512
#define GG 2048   // 4*H
#define H2 1024   // 2*H

// ---------------- scratch (device globals; no allocations allowed) -------------
__device__ float g_xg0[LL * BB * GG];     // forward  input gates  [t][b][4H]
__device__ float g_xg1[LL * BB * GG];     // backward input gates  [t][b][4H]
__device__ float g_Hout[BB * LL * H2];    // [b][l][2H]  (fwd | bwd)
__device__ float g_Hn[BB * LL * H2];      // Hout @ W_nov
__device__ float g_hbuf[2 * BB * HH];     // live hidden state per direction
__device__ float g_doc[BB * H2];
__device__ float g_D[BB * H2];
__device__ float g_S[BB * H2];
__device__ float g_base[BB * LL];
__device__ unsigned g_bar_count = 0;
__device__ unsigned g_bar_gen = 0;

// ---------------- grid-wide barrier (all CTAs co-resident by construction) ----
__device__ __forceinline__ void gsync(unsigned nb) {
    __threadfence();          // make this thread's global writes visible
    __syncthreads();
    if (threadIdx.x == 0) {
        unsigned old = *(volatile unsigned*)&g_bar_gen;
        if (atomicAdd(&g_bar_count, 1u) == nb - 1u) {
            *(volatile unsigned*)&g_bar_count = 0u;
            __threadfence();
            atomicAdd(&g_bar_gen, 1u);
        } else {
            while (*(volatile unsigned*)&g_bar_gen == old) { __nanosleep(64); }
        }
    }
    __syncthreads();
    __threadfence();          // gpu-scope fence: invalidates L1 (CCTL.IVALL)
}

__device__ __forceinline__ float sigm(float x) { return 1.f / (1.f + __expf(-x)); }

// ---------------- generic 128x128x16 SGEMM, 8x8 register tiles -----------------
// C[m,n] = sum_k A[m,k] * (BT ? Bm[n,k] : Bm[k,n]) + bias[n]
// REMAP: input rows are m = b*L + t; output row becomes t*B + b (for xg layout).
template <bool BT, bool REMAP>
__global__ __launch_bounds__(256) void k_gemm(
    const float* __restrict__ A, const float* __restrict__ Bm,
    const float* __restrict__ bias, float* __restrict__ C,
    int M, int N, int K)
{
    __shared__ float As[16][132];
    __shared__ float Bs[16][132];
    const int tid = threadIdx.x;
    const int bm = blockIdx.y * 128;
    const int bn = blockIdx.x * 128;
    const int ty = tid >> 4, tx = tid & 15;
    const int ar = tid >> 2, ak = (tid & 3) << 2;     // k-contiguous loads
    const int bkr = tid >> 5, bnc = (tid & 31) << 2;  // n-contiguous loads (NN)

    float acc[8][8];
#pragma unroll
    for (int i = 0; i < 8; i++)
#pragma unroll
        for (int j = 0; j < 8; j++) acc[i][j] = 0.f;

    for (int k0 = 0; k0 < K; k0 += 16) {
#pragma unroll
        for (int r = 0; r < 128; r += 64) {
            float4 v = *(const float4*)(A + (size_t)(bm + ar + r) * K + k0 + ak);
            As[ak + 0][ar + r] = v.x; As[ak + 1][ar + r] = v.y;
            As[ak + 2][ar + r] = v.z; As[ak + 3][ar + r] = v.w;
        }
        if (BT) {
#pragma unroll
            for (int r = 0; r < 128; r += 64) {
                float4 v = *(const float4*)(Bm + (size_t)(bn + ar + r) * K + k0 + ak);
                Bs[ak + 0][ar + r] = v.x; Bs[ak + 1][ar + r] = v.y;
                Bs[ak + 2][ar + r] = v.z; Bs[ak + 3][ar + r] = v.w;
            }
        } else {
#pragma unroll
            for (int r = 0; r < 16; r += 8) {
                float4 v = *(const float4*)(Bm + (size_t)(k0 + bkr + r) * N + bn + bnc);
                *(float4*)&Bs[bkr + r][bnc] = v;
            }
        }
        __syncthreads();
#pragma unroll
        for (int k = 0; k < 16; k++) {
            float a[8], bf[8];
            *(float4*)&a[0] = *(const float4*)&As[k][ty * 8];
            *(float4*)&a[4] = *(const float4*)&As[k][ty * 8 + 4];
            *(float4*)&bf[0] = *(const float4*)&Bs[k][tx * 8];
            *(float4*)&bf[4] = *(const float4*)&Bs[k][tx * 8 + 4];
#pragma unroll
            for (int i = 0; i < 8; i++)
#pragma unroll
                for (int j = 0; j < 8; j++) acc[i][j] += a[i] * bf[j];
        }
        __syncthreads();
    }

    float bv[8];
#pragma unroll
    for (int j = 0; j < 8; j++) bv[j] = bias ? bias[bn + tx * 8 + j] : 0.f;
#pragma unroll
    for (int i = 0; i < 8; i++) {
        int m = bm + ty * 8 + i;
        int row = REMAP ? ((m & (LL - 1)) * BB + (m >> 8)) : m;
        float* cp = C + (size_t)row * N + bn + tx * 8;
#pragma unroll
        for (int j = 0; j < 8; j++) cp[j] = acc[i][j] + bv[j];
    }
}

// ---------------- persistent bidirectional LSTM -------------------------------
// 128 CTAs: dir = cta>>6, seg = cta&63 -> owns h-units [seg*8, seg*8+8) of that
// direction (all 4 gates + cell state), full batch. Whh tile cached in smem.
__global__ __launch_bounds__(256, 1) void k_recurrent(
    const float* __restrict__ Whh_f, const float* __restrict__ Whh_b,
    const int* __restrict__ slen,
    const float* __restrict__ xg0, const float* __restrict__ xg1,
    float* __restrict__ hbuf, float* __restrict__ Hout)
{
    extern __shared__ float sm[];
    float* s_whh = sm;                    // [512][32]  (k-major)
    float* s_h   = sm + 16384;            // [64][512]
    float* s_z   = sm + 16384 + 32768;    // [64][32]
    float* s_c   = s_z + 2048;            // [512]  (b*8+u)

    const int tid = threadIdx.x;
    const int dir = blockIdx.x >> 6;
    const int seg = blockIdx.x & 63;
    const int hu0 = seg * 8;
    const unsigned nb = gridDim.x;
    const float* Whh = dir ? Whh_b : Whh_f;
    const float* xg  = dir ? xg1 : xg0;
    float* hglob = hbuf + dir * (BB * HH);

    // stage Whh rows for our 32 gate-rows (one-time; reused 256 steps)
    for (int g = 0; g < 32; g++) {
        const float* wr = Whh + (size_t)(((g >> 3) * HH) + hu0 + (g & 7)) * HH;
        for (int k = tid; k < HH; k += 256) s_whh[k * 32 + g] = wr[k];
    }
    for (int i = tid; i < 512; i += 256) s_c[i] = 0.f;
    for (int i = tid; i < 512; i += 256) {
        int b = i >> 3, u = i & 7;
        hglob[b * HH + hu0 + u] = 0.f;
    }
    gsync(nb);

    const int gi = tid & 31;           // gate-row within our 32
    const int b0 = (tid >> 5) * 8;     // 8 batch rows per thread

    for (int step = 0; step < LL; ++step) {
        const int t = dir ? (LL - 1 - step) : step;
        { // stage full h[64][512] for this direction
            const float4* hp = (const float4*)hglob;
            float4* sh4 = (float4*)s_h;
            for (int i = tid; i < BB * HH / 4; i += 256) sh4[i] = hp[i];
        }
        __syncthreads();

        float acc[8];
#pragma unroll
        for (int i = 0; i < 8; i++) acc[i] = 0.f;
        for (int k = 0; k < HH; k += 4) {
            float w0 = s_whh[(k + 0) * 32 + gi], w1 = s_whh[(k + 1) * 32 + gi];
            float w2 = s_whh[(k + 2) * 32 + gi], w3 = s_whh[(k + 3) * 32 + gi];
#pragma unroll
            for (int i = 0; i < 8; i++) {
                float4 h4 = *(const float4*)&s_h[(b0 + i) * HH + k];
                acc[i] += h4.x * w0 + h4.y * w1 + h4.z * w2 + h4.w * w3;
            }
        }
#pragma unroll
        for (int i = 0; i < 8; i++) s_z[(b0 + i) * 32 + gi] = acc[i];
        __syncthreads();

        for (int idx = tid; idx < 512; idx += 256) {
            int b = idx >> 3, u = idx & 7;
            const float* xp = xg + (size_t)(t * BB + b) * GG + hu0 + u;
            float zi = s_z[b * 32 + u]      + xp[0];
            float zf = s_z[b * 32 + 8 + u]  + xp[HH];
            float zg = s_z[b * 32 + 16 + u] + xp[2 * HH];
            float zo = s_z[b * 32 + 24 + u] + xp[3 * HH];
            float c  = s_c[idx];
            float cn = sigm(zf) * c + sigm(zi) * tanhf(zg);
            float hn = sigm(zo) * tanhf(cn);
            bool act = t < slen[b];
            if (act) { s_c[idx] = cn; hglob[b * HH + hu0 + u] = hn; }
            Hout[(size_t)(b * LL + t) * H2 + dir * HH + hu0 + u] = act ? hn : 0.f;
        }
        gsync(nb);
    }
}

// ---------------- epilogue kernels ---------------------------------------------
__global__ void k_docsum(const float* __restrict__ Hout,
                         const int* __restrict__ dlen, float* __restrict__ out)
{
    int b = blockIdx.x, tid = threadIdx.x;
    int dl = dlen[b];
    float acc[4] = {0.f, 0.f, 0.f, 0.f};
    for (int t = 0; t < dl; t++) {
        const float* hp = Hout + (size_t)(b * LL + t) * H2;
#pragma unroll
        for (int j = 0; j < 4; j++) acc[j] += hp[tid + j * 256];
    }
    float inv = 1.f / (float)dl;
#pragma unroll
    for (int j = 0; j < 4; j++) out[b * H2 + tid + j * 256] = acc[j] * inv;
}

// out[b][d] = dot(W[d,:], v[b,:]) + bias[d]
__global__ void k_mv(const float* __restrict__ W, const float* __restrict__ v,
                     const float* __restrict__ bias, float* __restrict__ out)
{
    int b = blockIdx.y;
    int wid = threadIdx.x >> 5, lane = threadIdx.x & 31;
    int d = blockIdx.x * 8 + wid;
    const float4* wp = (const float4*)(W + (size_t)d * H2);
    const float4* vp = (const float4*)(v + (size_t)b * H2);
    float acc = 0.f;
    for (int e = lane; e < H2 / 4; e += 32) {
        float4 a = wp[e], c = vp[e];
        acc += a.x * c.x + a.y * c.y + a.z * c.z + a.w * c.w;
    }
#pragma unroll
    for (int off = 16; off > 0; off >>= 1) acc += __shfl_down_sync(0xffffffffu, acc, off);
    if (lane == 0) out[b * H2 + d] = acc + (bias ? bias[d] : 0.f);
}

__global__ void k_base(const float* __restrict__ Hout, const float* __restrict__ S,
                       const float* __restrict__ w_con, const float* __restrict__ b_con,
                       const float* __restrict__ b_sal, const float* __restrict__ pos,
                       float* __restrict__ base)
{
    int b = blockIdx.x;
    int l = blockIdx.y * 8 + (threadIdx.x >> 5);
    int lane = threadIdx.x & 31;
    const float4* hp = (const float4*)(Hout + (size_t)(b * LL + l) * H2);
    const float4* wc = (const float4*)w_con;
    const float4* sp = (const float4*)(S + (size_t)b * H2);
    float a1 = 0.f, a2 = 0.f;
    for (int e = lane; e < H2 / 4; e += 32) {
        float4 h = hp[e], w = wc[e], s = sp[e];
        a1 += h.x * w.x + h.y * w.y + h.z * w.z + h.w * w.w;
        a2 += h.x * s.x + h.y * s.y + h.z * s.z + h.w * s.w;
    }
#pragma unroll
    for (int off = 16; off > 0; off >>= 1) {
        a1 += __shfl_down_sync(0xffffffffu, a1, off);
        a2 += __shfl_down_sync(0xffffffffu, a2, off);
    }
    if (lane == 0) base[b * LL + l] = a1 + a2 + b_con[0] + b_sal[0] + pos[l];
}

__global__ void k_scan(const float* __restrict__ Hout, const float* __restrict__ Hn,
                       const float* __restrict__ base, const float* __restrict__ b_nov,
                       const float* __restrict__ w_cls, const float* __restrict__ b_cls,
                       float* __restrict__ out)
{
    __shared__ float s[H2];
    __shared__ float red[8];
    __shared__ float p_sh;
    int b = blockIdx.x, tid = threadIdx.x, lane = tid & 31, wid = tid >> 5;
#pragma unroll
    for (int j = 0; j < 4; j++) s[tid + j * 256] = 0.f;
    float wcls = w_cls[0], bcls = b_cls[0], bnov = b_nov[0];
    __syncthreads();
    for (int i = 0; i < LL; i++) {
        const float* hn = Hn + (size_t)(b * LL + i) * H2;
        float part = 0.f;
#pragma unroll
        for (int j = 0; j < 4; j++) part += hn[tid + j * 256] * s[tid + j * 256];
#pragma unroll
        for (int off = 16; off > 0; off >>= 1) part += __shfl_down_sync(0xffffffffu, part, off);
        if (lane == 0) red[wid] = part;
        __syncthreads();
        if (tid == 0) {
            float tot = 0.f;
#pragma unroll
            for (int w = 0; w < 8; w++) tot += red[w];
            float nov = (i == 0) ? 0.f : (tot + bnov);
            float p = 1.f / (1.f + __expf(-(wcls * (base[b * LL + i] + nov) + bcls)));
            p_sh = p;
            out[b * LL + i] = p;
        }
        __syncthreads();
        float p = p_sh;
        const float* ho = Hout + (size_t)(b * LL + i) * H2;
#pragma unroll
        for (int j = 0; j < 4; j++) s[tid + j * 256] += ho[tid + j * 256] * p;
        __syncthreads();
    }
}

// ---------------- launch --------------------------------------------------------
extern "C" void kernel_launch(void* const* d_in, const int* in_sizes, int n_in,
                              void* d_out, int out_size)
{
    (void)in_sizes; (void)n_in; (void)out_size;
    const float* x     = (const float*)d_in[0];
    const int*   slen  = (const int*)  d_in[1];
    const int*   dlen  = (const int*)  d_in[2];
    const float* Wih_f = (const float*)d_in[3];
    const float* Whh_f = (const float*)d_in[4];
    const float* b_f   = (const float*)d_in[5];
    const float* Wih_b = (const float*)d_in[6];
    const float* Whh_b = (const float*)d_in[7];
    const float* b_b   = (const float*)d_in[8];
    const float* W_doc = (const float*)d_in[9];
    const float* b_doc = (const float*)d_in[10];
    const float* w_con = (const float*)d_in[11];
    const float* b_con = (const float*)d_in[12];
    const float* W_sal = (const float*)d_in[13];
    const float* b_sal = (const float*)d_in[14];
    const float* W_nov = (const float*)d_in[15];
    const float* b_nov = (const float*)d_in[16];
    const float* pos   = (const float*)d_in[17];
    const float* w_cls = (const float*)d_in[18];
    const float* b_cls = (const float*)d_in[19];
    float* out = (float*)d_out;

    float *p_xg0, *p_xg1, *p_Hout, *p_Hn, *p_hbuf, *p_doc, *p_D, *p_S, *p_base;
    cudaGetSymbolAddress((void**)&p_xg0,  g_xg0);
    cudaGetSymbolAddress((void**)&p_xg1,  g_xg1);
    cudaGetSymbolAddress((void**)&p_Hout, g_Hout);
    cudaGetSymbolAddress((void**)&p_Hn,   g_Hn);
    cudaGetSymbolAddress((void**)&p_hbuf, g_hbuf);
    cudaGetSymbolAddress((void**)&p_doc,  g_doc);
    cudaGetSymbolAddress((void**)&p_D,    g_D);
    cudaGetSymbolAddress((void**)&p_S,    g_S);
    cudaGetSymbolAddress((void**)&p_base, g_base);

    const int M = BB * LL;  // 16384

    // 1) input projections (NT GEMM, remapped to [t][b][4H], bias fused)
    k_gemm<true, true><<<dim3(GG / 128, M / 128), 256>>>(x, Wih_f, b_f, p_xg0, M, GG, EE);
    k_gemm<true, true><<<dim3(GG / 128, M / 128), 256>>>(x, Wih_b, b_b, p_xg1, M, GG, EE);

    // 2) bidirectional LSTM (persistent, 128 CTAs, 202KB smem each)
    const int REC_SMEM = (16384 + 32768 + 2048 + 512) * 4;
    cudaFuncSetAttribute(k_recurrent, cudaFuncAttributeMaxDynamicSharedMemorySize, REC_SMEM);
    k_recurrent<<<128, 256, REC_SMEM>>>(Whh_f, Whh_b, slen, p_xg0, p_xg1, p_hbuf, p_Hout);

    // 3) doc representation + salience transform
    k_docsum<<<BB, 256>>>(p_Hout, dlen, p_doc);
    k_mv<<<dim3(H2 / 8, BB), 256>>>(W_doc, p_doc, b_doc, p_D);
    k_mv<<<dim3(H2 / 8, BB), 256>>>(W_sal, p_D, nullptr, p_S);

    // 4) novelty precompute (NN GEMM)
    k_gemm<false, false><<<dim3(H2 / 128, M / 128), 256>>>(p_Hout, W_nov, nullptr, p_Hn, M, H2, H2);

    // 5) base scores, then the sequential probability scan
    k_base<<<dim3(BB, LL / 8), 256>>>(p_Hout, p_S, w_con, b_con, b_sal, pos, p_base);
    k_scan<<<BB, 256>>>(p_Hout, p_Hn, p_base, b_nov, w_cls, b_cls, out);
}

// round 2
// speedup vs baseline: 1.2670x; 1.2670x over previous
#include <cuda_runtime.h>
#include <cuda_bf16.h>
#include <math.h>
#include <stdint.h>

#define BB 64
#define LL 256
#define EE 512
#define HH 512
#define GG 2048   // 4*H
#define H2 1024   // 2*H

// ---------------- scratch (device globals; no allocations allowed) -------------
__device__ float g_xg0[LL * BB * GG];     // forward  input gates  [t][b][4H]
__device__ float g_xg1[LL * BB * GG];     // backward input gates  [t][b][4H]
__device__ float g_Hout[BB * LL * H2];    // [b][l][2H]  (fwd | bwd)
__device__ float g_Hn[BB * LL * H2];      // Hout @ W_nov
__device__ float g_WnT[H2 * H2];          // W_nov transposed
__device__ float g_hbuf[2 * BB * HH];     // live hidden state per direction
__device__ float g_doc[BB * H2];
__device__ float g_D[BB * H2];
__device__ float g_S[BB * H2];
__device__ float g_base[BB * LL];
__device__ unsigned g_bar_count = 0;
__device__ unsigned g_bar_gen = 0;

// ---------------- grid-wide barrier (all CTAs co-resident by construction) ----
__device__ __forceinline__ void gsync(unsigned nb) {
    __threadfence();
    __syncthreads();
    if (threadIdx.x == 0) {
        unsigned old = *(volatile unsigned*)&g_bar_gen;
        if (atomicAdd(&g_bar_count, 1u) == nb - 1u) {
            *(volatile unsigned*)&g_bar_count = 0u;
            __threadfence();
            atomicAdd(&g_bar_gen, 1u);
        } else {
            while (*(volatile unsigned*)&g_bar_gen == old) { __nanosleep(64); }
        }
    }
    __syncthreads();
    __threadfence();
}

__device__ __forceinline__ float sigm(float x) { return 1.f / (1.f + __expf(-x)); }

__device__ __forceinline__ uint32_t f2tf(float f) {
    uint32_t u; asm("cvt.rna.tf32.f32 %0, %1;" : "=r"(u) : "f"(f)); return u;
}

__device__ __forceinline__ void mma_tf32(float* c, const uint32_t* a, const uint32_t* b) {
    asm volatile(
        "mma.sync.aligned.m16n8k8.row.col.f32.tf32.tf32.f32 "
        "{%0,%1,%2,%3}, {%4,%5,%6,%7}, {%8,%9}, {%0,%1,%2,%3};"
        : "+f"(c[0]), "+f"(c[1]), "+f"(c[2]), "+f"(c[3])
        : "r"(a[0]), "r"(a[1]), "r"(a[2]), "r"(a[3]), "r"(b[0]), "r"(b[1]));
}

// ---------------- tf32 tensor-core GEMM: C[m,n] = A[m,:] . Bt[n,:] + bias[n] ---
// CTA tile 128x128, K-step 32. 8 warps (2 x 4), warp tile 64x32, mma m16n8k8.
// REMAP: input rows m = b*L + t; output row becomes t*B + b (for xg layout).
template <bool REMAP>
__global__ __launch_bounds__(256, 2) void k_gemm_tf32(
    const float* __restrict__ A, const float* __restrict__ Bt,
    const float* __restrict__ bias, float* __restrict__ C,
    int M, int N, int K)
{
    __shared__ uint32_t As[128 * 36];
    __shared__ uint32_t Bs[128 * 36];
    const int tid = threadIdx.x;
    const int lane = tid & 31;
    const int warp = tid >> 5;
    const int wm = warp >> 2;            // 0..1 -> 64-row slab
    const int wn = warp & 3;             // 0..3 -> 32-col slab
    const int g  = lane >> 2;            // group id 0..7
    const int tg = lane & 3;             // thread-in-group
    const int bm = blockIdx.y * 128;
    const int bn = blockIdx.x * 128;

    const int srow = tid >> 3;           // staging row 0..31 (+32*r)
    const int scol = (tid & 7) << 2;     // staging k 0..28 step 4

    float acc[4][4][4];
#pragma unroll
    for (int i = 0; i < 4; i++)
#pragma unroll
        for (int j = 0; j < 4; j++)
#pragma unroll
            for (int e = 0; e < 4; e++) acc[i][j][e] = 0.f;

    for (int k0 = 0; k0 < K; k0 += 32) {
#pragma unroll
        for (int r = 0; r < 4; r++) {
            int row = srow + 32 * r;
            float4 va = *(const float4*)(A + (size_t)(bm + row) * K + k0 + scol);
            uint32_t* ap = &As[row * 36 + scol];
            ap[0] = f2tf(va.x); ap[1] = f2tf(va.y); ap[2] = f2tf(va.z); ap[3] = f2tf(va.w);
            float4 vb = *(const float4*)(Bt + (size_t)(bn + row) * K + k0 + scol);
            uint32_t* bp = &Bs[row * 36 + scol];
            bp[0] = f2tf(vb.x); bp[1] = f2tf(vb.y); bp[2] = f2tf(vb.z); bp[3] = f2tf(vb.w);
        }
        __syncthreads();

#pragma unroll
        for (int kk = 0; kk < 32; kk += 8) {
            uint32_t a[4][4], b[4][2];
#pragma unroll
            for (int i = 0; i < 4; i++) {
                int base = wm * 64 + i * 16;
                a[i][0] = As[(base + g)     * 36 + kk + tg];
                a[i][1] = As[(base + g + 8) * 36 + kk + tg];
                a[i][2] = As[(base + g)     * 36 + kk + tg + 4];
                a[i][3] = As[(base + g + 8) * 36 + kk + tg + 4];
            }
#pragma unroll
            for (int j = 0; j < 4; j++) {
                int nb = wn * 32 + j * 8;
                b[j][0] = Bs[(nb + g) * 36 + kk + tg];
                b[j][1] = Bs[(nb + g) * 36 + kk + tg + 4];
            }
#pragma unroll
            for (int i = 0; i < 4; i++)
#pragma unroll
                for (int j = 0; j < 4; j++) mma_tf32(acc[i][j], a[i], b[j]);
        }
        __syncthreads();
    }

    // epilogue: c0/c1 at (g, tg*2 / +1), c2/c3 at (g+8, ...)
#pragma unroll
    for (int i = 0; i < 4; i++) {
#pragma unroll
        for (int j = 0; j < 4; j++) {
            int col = bn + wn * 32 + j * 8 + tg * 2;
            float bv0 = bias ? bias[col] : 0.f;
            float bv1 = bias ? bias[col + 1] : 0.f;
            int m0 = bm + wm * 64 + i * 16 + g;
            int m1 = m0 + 8;
            int r0 = REMAP ? ((m0 & (LL - 1)) * BB + (m0 >> 8)) : m0;
            int r1 = REMAP ? ((m1 & (LL - 1)) * BB + (m1 >> 8)) : m1;
            float2 v0 = make_float2(acc[i][j][0] + bv0, acc[i][j][1] + bv1);
            float2 v1 = make_float2(acc[i][j][2] + bv0, acc[i][j][3] + bv1);
            *(float2*)(C + (size_t)r0 * N + col) = v0;
            *(float2*)(C + (size_t)r1 * N + col) = v1;
        }
    }
}

// ---------------- 1024x1024 transpose (W_nov -> k-major) -----------------------
__global__ void k_transpose(const float* __restrict__ in, float* __restrict__ out) {
    __shared__ float t[32][33];
    int bx = blockIdx.x * 32, by = blockIdx.y * 32;
    int x = threadIdx.x, y = threadIdx.y;
#pragma unroll
    for (int j = 0; j < 32; j += 8) t[y + j][x] = in[(size_t)(by + y + j) * H2 + bx + x];
    __syncthreads();
#pragma unroll
    for (int j = 0; j < 32; j += 8) out[(size_t)(bx + y + j) * H2 + by + x] = t[x][y + j];
}

// ---------------- persistent bidirectional LSTM -------------------------------
__global__ __launch_bounds__(256, 1) void k_recurrent(
    const float* __restrict__ Whh_f, const float* __restrict__ Whh_b,
    const int* __restrict__ slen,
    const float* __restrict__ xg0, const float* __restrict__ xg1,
    float* __restrict__ hbuf, float* __restrict__ Hout)
{
    extern __shared__ float sm[];
    float* s_whh = sm;                    // [512][32]  (k-major)
    float* s_h   = sm + 16384;            // [64][512]
    float* s_z   = sm + 16384 + 32768;    // [64][32]
    float* s_c   = s_z + 2048;            // [512]

    const int tid = threadIdx.x;
    const int dir = blockIdx.x >> 6;
    const int seg = blockIdx.x & 63;
    const int hu0 = seg * 8;
    const unsigned nb = gridDim.x;
    const float* Whh = dir ? Whh_b : Whh_f;
    const float* xg  = dir ? xg1 : xg0;
    float* hglob = hbuf + dir * (BB * HH);

    for (int gg = 0; gg < 32; gg++) {
        const float* wr = Whh + (size_t)(((gg >> 3) * HH) + hu0 + (gg & 7)) * HH;
        for (int k = tid; k < HH; k += 256) s_whh[k * 32 + gg] = wr[k];
    }
    for (int i = tid; i < 512; i += 256) s_c[i] = 0.f;
    for (int i = tid; i < 512; i += 256) {
        int b = i >> 3, u = i & 7;
        hglob[b * HH + hu0 + u] = 0.f;
    }
    gsync(nb);

    const int gi = tid & 31;
    const int b0 = (tid >> 5) * 8;

    for (int step = 0; step < LL; ++step) {
        const int t = dir ? (LL - 1 - step) : step;
        {
            const float4* hp = (const float4*)hglob;
            float4* sh4 = (float4*)s_h;
            for (int i = tid; i < BB * HH / 4; i += 256) sh4[i] = hp[i];
        }
        __syncthreads();

        float acc[8];
#pragma unroll
        for (int i = 0; i < 8; i++) acc[i] = 0.f;
        for (int k = 0; k < HH; k += 4) {
            float w0 = s_whh[(k + 0) * 32 + gi], w1 = s_whh[(k + 1) * 32 + gi];
            float w2 = s_whh[(k + 2) * 32 + gi], w3 = s_whh[(k + 3) * 32 + gi];
#pragma unroll
            for (int i = 0; i < 8; i++) {
                float4 h4 = *(const float4*)&s_h[(b0 + i) * HH + k];
                acc[i] += h4.x * w0 + h4.y * w1 + h4.z * w2 + h4.w * w3;
            }
        }
#pragma unroll
        for (int i = 0; i < 8; i++) s_z[(b0 + i) * 32 + gi] = acc[i];
        __syncthreads();

        for (int idx = tid; idx < 512; idx += 256) {
            int b = idx >> 3, u = idx & 7;
            const float* xp = xg + (size_t)(t * BB + b) * GG + hu0 + u;
            float zi = s_z[b * 32 + u]      + xp[0];
            float zf = s_z[b * 32 + 8 + u]  + xp[HH];
            float zg = s_z[b * 32 + 16 + u] + xp[2 * HH];
            float zo = s_z[b * 32 + 24 + u] + xp[3 * HH];
            float c  = s_c[idx];
            float cn = sigm(zf) * c + sigm(zi) * tanhf(zg);
            float hn = sigm(zo) * tanhf(cn);
            bool act = t < slen[b];
            if (act) { s_c[idx] = cn; hglob[b * HH + hu0 + u] = hn; }
            Hout[(size_t)(b * LL + t) * H2 + dir * HH + hu0 + u] = act ? hn : 0.f;
        }
        gsync(nb);
    }
}

// ---------------- epilogue kernels ---------------------------------------------
__global__ void k_docsum(const float* __restrict__ Hout,
                         const int* __restrict__ dlen, float* __restrict__ out)
{
    int b = blockIdx.x, tid = threadIdx.x;
    int dl = dlen[b];
    float acc[4] = {0.f, 0.f, 0.f, 0.f};
    for (int t = 0; t < dl; t++) {
        const float* hp = Hout + (size_t)(b * LL + t) * H2;
#pragma unroll
        for (int j = 0; j < 4; j++) acc[j] += hp[tid + j * 256];
    }
    float inv = 1.f / (float)dl;
#pragma unroll
    for (int j = 0; j < 4; j++) out[b * H2 + tid + j * 256] = acc[j] * inv;
}

__global__ void k_mv(const float* __restrict__ W, const float* __restrict__ v,
                     const float* __restrict__ bias, float* __restrict__ out)
{
    int b = blockIdx.y;
    int wid = threadIdx.x >> 5, lane = threadIdx.x & 31;
    int d = blockIdx.x * 8 + wid;
    const float4* wp = (const float4*)(W + (size_t)d * H2);
    const float4* vp = (const float4*)(v + (size_t)b * H2);
    float acc = 0.f;
    for (int e = lane; e < H2 / 4; e += 32) {
        float4 a = wp[e], c = vp[e];
        acc += a.x * c.x + a.y * c.y + a.z * c.z + a.w * c.w;
    }
#pragma unroll
    for (int off = 16; off > 0; off >>= 1) acc += __shfl_down_sync(0xffffffffu, acc, off);
    if (lane == 0) out[b * H2 + d] = acc + (bias ? bias[d] : 0.f);
}

__global__ void k_base(const float* __restrict__ Hout, const float* __restrict__ S,
                       const float* __restrict__ w_con, const float* __restrict__ b_con,
                       const float* __restrict__ b_sal, const float* __restrict__ pos,
                       float* __restrict__ base)
{
    int b = blockIdx.x;
    int l = blockIdx.y * 8 + (threadIdx.x >> 5);
    int lane = threadIdx.x & 31;
    const float4* hp = (const float4*)(Hout + (size_t)(b * LL + l) * H2);
    const float4* wc = (const float4*)w_con;
    const float4* sp = (const float4*)(S + (size_t)b * H2);
    float a1 = 0.f, a2 = 0.f;
    for (int e = lane; e < H2 / 4; e += 32) {
        float4 h = hp[e], w = wc[e], s = sp[e];
        a1 += h.x * w.x + h.y * w.y + h.z * w.z + h.w * w.w;
        a2 += h.x * s.x + h.y * s.y + h.z * s.z + h.w * s.w;
    }
#pragma unroll
    for (int off = 16; off > 0; off >>= 1) {
        a1 += __shfl_down_sync(0xffffffffu, a1, off);
        a2 += __shfl_down_sync(0xffffffffu, a2, off);
    }
    if (lane == 0) base[b * LL + l] = a1 + a2 + b_con[0] + b_sal[0] + pos[l];
}

__global__ void k_scan(const float* __restrict__ Hout, const float* __restrict__ Hn,
                       const float* __restrict__ base, const float* __restrict__ b_nov,
                       const float* __restrict__ w_cls, const float* __restrict__ b_cls,
                       float* __restrict__ out)
{
    __shared__ float s[H2];
    __shared__ float red[8];
    __shared__ float p_sh;
    int b = blockIdx.x, tid = threadIdx.x, lane = tid & 31, wid = tid >> 5;
#pragma unroll
    for (int j = 0; j < 4; j++) s[tid + j * 256] = 0.f;
    float wcls = w_cls[0], bcls = b_cls[0], bnov = b_nov[0];
    __syncthreads();
    for (int i = 0; i < LL; i++) {
        const float* hn = Hn + (size_t)(b * LL + i) * H2;
        float part = 0.f;
#pragma unroll
        for (int j = 0; j < 4; j++) part += hn[tid + j * 256] * s[tid + j * 256];
#pragma unroll
        for (int off = 16; off > 0; off >>= 1) part += __shfl_down_sync(0xffffffffu, part, off);
        if (lane == 0) red[wid] = part;
        __syncthreads();
        if (tid == 0) {
            float tot = 0.f;
#pragma unroll
            for (int w = 0; w < 8; w++) tot += red[w];
            float nov = (i == 0) ? 0.f : (tot + bnov);
            float p = 1.f / (1.f + __expf(-(wcls * (base[b * LL + i] + nov) + bcls)));
            p_sh = p;
            out[b * LL + i] = p;
        }
        __syncthreads();
        float p = p_sh;
        const float* ho = Hout + (size_t)(b * LL + i) * H2;
#pragma unroll
        for (int j = 0; j < 4; j++) s[tid + j * 256] += ho[tid + j * 256] * p;
        __syncthreads();
    }
}

// ---------------- launch --------------------------------------------------------
extern "C" void kernel_launch(void* const* d_in, const int* in_sizes, int n_in,
                              void* d_out, int out_size)
{
    (void)in_sizes; (void)n_in; (void)out_size;
    const float* x     = (const float*)d_in[0];
    const int*   slen  = (const int*)  d_in[1];
    const int*   dlen  = (const int*)  d_in[2];
    const float* Wih_f = (const float*)d_in[3];
    const float* Whh_f = (const float*)d_in[4];
    const float* b_f   = (const float*)d_in[5];
    const float* Wih_b = (const float*)d_in[6];
    const float* Whh_b = (const float*)d_in[7];
    const float* b_b   = (const float*)d_in[8];
    const float* W_doc = (const float*)d_in[9];
    const float* b_doc = (const float*)d_in[10];
    const float* w_con = (const float*)d_in[11];
    const float* b_con = (const float*)d_in[12];
    const float* W_sal = (const float*)d_in[13];
    const float* b_sal = (const float*)d_in[14];
    const float* W_nov = (const float*)d_in[15];
    const float* b_nov = (const float*)d_in[16];
    const float* pos   = (const float*)d_in[17];
    const float* w_cls = (const float*)d_in[18];
    const float* b_cls = (const float*)d_in[19];
    float* out = (float*)d_out;

    float *p_xg0, *p_xg1, *p_Hout, *p_Hn, *p_WnT, *p_hbuf, *p_doc, *p_D, *p_S, *p_base;
    cudaGetSymbolAddress((void**)&p_xg0,  g_xg0);
    cudaGetSymbolAddress((void**)&p_xg1,  g_xg1);
    cudaGetSymbolAddress((void**)&p_Hout, g_Hout);
    cudaGetSymbolAddress((void**)&p_Hn,   g_Hn);
    cudaGetSymbolAddress((void**)&p_WnT,  g_WnT);
    cudaGetSymbolAddress((void**)&p_hbuf, g_hbuf);
    cudaGetSymbolAddress((void**)&p_doc,  g_doc);
    cudaGetSymbolAddress((void**)&p_D,    g_D);
    cudaGetSymbolAddress((void**)&p_S,    g_S);
    cudaGetSymbolAddress((void**)&p_base, g_base);

    const int M = BB * LL;  // 16384

    // 1) input projections on tf32 tensor cores (NT GEMM, remapped, bias fused)
    k_gemm_tf32<true><<<dim3(GG / 128, M / 128), 256>>>(x, Wih_f, b_f, p_xg0, M, GG, EE);
    k_gemm_tf32<true><<<dim3(GG / 128, M / 128), 256>>>(x, Wih_b, b_b, p_xg1, M, GG, EE);

    // transpose W_nov now (independent of LSTM)
    k_transpose<<<dim3(32, 32), dim3(32, 8)>>>(W_nov, p_WnT);

    // 2) bidirectional LSTM (persistent, 128 CTAs)
    const int REC_SMEM = (16384 + 32768 + 2048 + 512) * 4;
    cudaFuncSetAttribute(k_recurrent, cudaFuncAttributeMaxDynamicSharedMemorySize, REC_SMEM);
    k_recurrent<<<128, 256, REC_SMEM>>>(Whh_f, Whh_b, slen, p_xg0, p_xg1, p_hbuf, p_Hout);

    // 3) doc representation + salience transform
    k_docsum<<<BB, 256>>>(p_Hout, dlen, p_doc);
    k_mv<<<dim3(H2 / 8, BB), 256>>>(W_doc, p_doc, b_doc, p_D);
    k_mv<<<dim3(H2 / 8, BB), 256>>>(W_sal, p_D, nullptr, p_S);

    // 4) novelty precompute on tf32 tensor cores (NT with transposed W_nov)
    k_gemm_tf32<false><<<dim3(H2 / 128, M / 128), 256>>>(p_Hout, p_WnT, nullptr, p_Hn, M, H2, H2);

    // 5) base scores, then the sequential probability scan
    k_base<<<dim3(BB, LL / 8), 256>>>(p_Hout, p_S, w_con, b_con, b_sal, pos, p_base);
    k_scan<<<BB, 256>>>(p_Hout, p_Hn, p_base, b_nov, w_cls, b_cls, out);
}

// round 3
// speedup vs baseline: 2.0048x; 1.5823x over previous
#include <cuda_runtime.h>
#include <cuda_bf16.h>
#include <math.h>
#include <stdint.h>

#define BB 64
#define LL 256
#define EE 512
#define HH 512
#define GG 2048   // 4*H
#define H2 1024   // 2*H
#define REC_PAD 516

// ---------------- scratch (device globals; no allocations allowed) -------------
__device__ float g_xg0[LL * BB * GG];
__device__ float g_xg1[LL * BB * GG];
__device__ float g_Hout[BB * LL * H2];
__device__ float g_Hn[BB * LL * H2];
__device__ float g_WnT[H2 * H2];
__device__ float g_hbuf[2 * BB * HH];
__device__ float g_docpart[8 * BB * H2];
__device__ float g_doc[BB * H2];
__device__ float g_D[BB * H2];
__device__ float g_S[BB * H2];
__device__ float g_base[BB * LL];
__device__ unsigned g_cnt1[8];
__device__ unsigned g_cnt2;
__device__ unsigned g_gen;

// ---------------- two-level tree barrier (128 CTAs, replay-safe) ---------------
__device__ __forceinline__ void gsync_tree(int cta) {
    __syncthreads();
    if (threadIdx.x == 0) {
        __threadfence();
        unsigned old = *(volatile unsigned*)&g_gen;
        bool done = false;
        if (atomicInc(&g_cnt1[cta & 7], 15u) == 15u) {       // wraps to 0
            if (atomicInc(&g_cnt2, 7u) == 7u) {              // wraps to 0
                __threadfence();
                atomicAdd(&g_gen, 1u);
                done = true;
            }
        }
        if (!done) while (*(volatile unsigned*)&g_gen == old) __nanosleep(32);
    }
    __syncthreads();
    __threadfence();
}

__device__ __forceinline__ float sigm(float x) { return 1.f / (1.f + __expf(-x)); }

__device__ __forceinline__ uint32_t f2tf(float f) {
    uint32_t u; asm("cvt.rna.tf32.f32 %0, %1;" : "=r"(u) : "f"(f)); return u;
}

__device__ __forceinline__ void mma_tf32(float* c, const uint32_t* a, const uint32_t* b) {
    asm volatile(
        "mma.sync.aligned.m16n8k8.row.col.f32.tf32.tf32.f32 "
        "{%0,%1,%2,%3}, {%4,%5,%6,%7}, {%8,%9}, {%0,%1,%2,%3};"
        : "+f"(c[0]), "+f"(c[1]), "+f"(c[2]), "+f"(c[3])
        : "r"(a[0]), "r"(a[1]), "r"(a[2]), "r"(a[3]), "r"(b[0]), "r"(b[1]));
}

// ---------------- tf32 tensor-core GEMM (as round 2, validated) ----------------
template <bool REMAP>
__global__ __launch_bounds__(256, 2) void k_gemm_tf32(
    const float* __restrict__ A, const float* __restrict__ Bt,
    const float* __restrict__ bias, float* __restrict__ C,
    int M, int N, int K)
{
    __shared__ uint32_t As[128 * 36];
    __shared__ uint32_t Bs[128 * 36];
    const int tid = threadIdx.x;
    const int lane = tid & 31;
    const int warp = tid >> 5;
    const int wm = warp >> 2;
    const int wn = warp & 3;
    const int g  = lane >> 2;
    const int tg = lane & 3;
    const int bm = blockIdx.y * 128;
    const int bn = blockIdx.x * 128;
    const int srow = tid >> 3;
    const int scol = (tid & 7) << 2;

    float acc[4][4][4];
#pragma unroll
    for (int i = 0; i < 4; i++)
#pragma unroll
        for (int j = 0; j < 4; j++)
#pragma unroll
            for (int e = 0; e < 4; e++) acc[i][j][e] = 0.f;

    for (int k0 = 0; k0 < K; k0 += 32) {
#pragma unroll
        for (int r = 0; r < 4; r++) {
            int row = srow + 32 * r;
            float4 va = *(const float4*)(A + (size_t)(bm + row) * K + k0 + scol);
            uint32_t* ap = &As[row * 36 + scol];
            ap[0] = f2tf(va.x); ap[1] = f2tf(va.y); ap[2] = f2tf(va.z); ap[3] = f2tf(va.w);
            float4 vb = *(const float4*)(Bt + (size_t)(bn + row) * K + k0 + scol);
            uint32_t* bp = &Bs[row * 36 + scol];
            bp[0] = f2tf(vb.x); bp[1] = f2tf(vb.y); bp[2] = f2tf(vb.z); bp[3] = f2tf(vb.w);
        }
        __syncthreads();
#pragma unroll
        for (int kk = 0; kk < 32; kk += 8) {
            uint32_t a[4][4], b[4][2];
#pragma unroll
            for (int i = 0; i < 4; i++) {
                int base = wm * 64 + i * 16;
                a[i][0] = As[(base + g)     * 36 + kk + tg];
                a[i][1] = As[(base + g + 8) * 36 + kk + tg];
                a[i][2] = As[(base + g)     * 36 + kk + tg + 4];
                a[i][3] = As[(base + g + 8) * 36 + kk + tg + 4];
            }
#pragma unroll
            for (int j = 0; j < 4; j++) {
                int nb = wn * 32 + j * 8;
                b[j][0] = Bs[(nb + g) * 36 + kk + tg];
                b[j][1] = Bs[(nb + g) * 36 + kk + tg + 4];
            }
#pragma unroll
            for (int i = 0; i < 4; i++)
#pragma unroll
                for (int j = 0; j < 4; j++) mma_tf32(acc[i][j], a[i], b[j]);
        }
        __syncthreads();
    }
#pragma unroll
    for (int i = 0; i < 4; i++) {
#pragma unroll
        for (int j = 0; j < 4; j++) {
            int col = bn + wn * 32 + j * 8 + tg * 2;
            float bv0 = bias ? bias[col] : 0.f;
            float bv1 = bias ? bias[col + 1] : 0.f;
            int m0 = bm + wm * 64 + i * 16 + g;
            int m1 = m0 + 8;
            int r0 = REMAP ? ((m0 & (LL - 1)) * BB + (m0 >> 8)) : m0;
            int r1 = REMAP ? ((m1 & (LL - 1)) * BB + (m1 >> 8)) : m1;
            *(float2*)(C + (size_t)r0 * N + col) = make_float2(acc[i][j][0] + bv0, acc[i][j][1] + bv1);
            *(float2*)(C + (size_t)r1 * N + col) = make_float2(acc[i][j][2] + bv0, acc[i][j][3] + bv1);
        }
    }
}

// ---------------- 1024x1024 transpose ------------------------------------------
__global__ void k_transpose(const float* __restrict__ in, float* __restrict__ out) {
    __shared__ float t[32][33];
    int bx = blockIdx.x * 32, by = blockIdx.y * 32;
    int x = threadIdx.x, y = threadIdx.y;
#pragma unroll
    for (int j = 0; j < 32; j += 8) t[y + j][x] = in[(size_t)(by + y + j) * H2 + bx + x];
    __syncthreads();
#pragma unroll
    for (int j = 0; j < 32; j += 8) out[(size_t)(bx + y + j) * H2 + by + x] = t[x][y + j];
}

// ---------------- persistent bidirectional LSTM, tf32 mma ----------------------
// 128 CTAs: dir = cta>>6, seg = cta&63 -> 32 gate-cols (8 units x 4 gates).
// Per step per CTA: z[64,32] = h[64,512] @ W[32,512]^T on tensor cores.
__global__ __launch_bounds__(256, 1) void k_recurrent(
    const float* __restrict__ Whh_f, const float* __restrict__ Whh_b,
    const int* __restrict__ slen,
    const float* __restrict__ xg0, const float* __restrict__ xg1,
    float* __restrict__ hbuf, float* __restrict__ Hout)
{
    extern __shared__ float sm[];
    uint32_t* s_h  = (uint32_t*)sm;                    // [64][516] tf32
    uint32_t* s_wf = (uint32_t*)sm + 64 * REC_PAD;     // [4][64][64] frag-major Whh
    float* s_z = sm + 64 * REC_PAD + 16384;            // [64][36]
    float* s_c = s_z + 64 * 36;                        // [512]

    const int tid = threadIdx.x;
    const int lane = tid & 31;
    const int warp = tid >> 5;
    const int wm = warp & 3;            // m-frag (batch rows wm*16..+15)
    const int wn = warp >> 2;           // n-half (gate cols wn*16..+15)
    const int g  = lane >> 2;
    const int tg = lane & 3;
    const int dir = blockIdx.x >> 6;
    const int seg = blockIdx.x & 63;
    const int hu0 = seg * 8;
    const float* Whh = dir ? Whh_b : Whh_f;
    const float* xg  = dir ? xg1 : xg0;
    float* hglob = hbuf + dir * (BB * HH);

    // one-time: pack Whh fragments (tf32, fragment-major)
    for (int s = tid; s < 16384; s += 256) {
        int reg = s & 1;
        int l   = (s >> 1) & 31;
        int kk  = (s >> 6) & 63;
        int fi  = s >> 12;                 // (wn*2 + j)
        int n   = (fi >> 1) * 16 + (fi & 1) * 8 + (l >> 2);
        int k   = kk * 8 + (l & 3) + reg * 4;
        int gate = n >> 3, unit = hu0 + (n & 7);
        s_wf[s] = f2tf(Whh[(size_t)(gate * HH + unit) * HH + k]);
    }
    for (int i = tid; i < 512; i += 256) s_c[i] = 0.f;
    for (int i = tid; i < 512; i += 256) {
        int b = i >> 3, u = i & 7;
        hglob[b * HH + hu0 + u] = 0.f;
    }
    gsync_tree(blockIdx.x);

    const int sl0 = slen[tid >> 3];
    const int sl1 = slen[(tid >> 3) + 32];

    const int o0 = g * REC_PAD + tg;          // a0
    const int o1 = o0 + 8 * REC_PAD;          // a1
    const uint32_t* b0base = s_wf + (wn * 2) * 4096 + lane * 2;
    const uint32_t* b1base = b0base + 4096;

    for (int step = 0; step < LL; ++step) {
        const int t = dir ? (LL - 1 - step) : step;

        // stage h -> smem as tf32 (L2-coherent reads)
        for (int i = tid; i < 8192; i += 256) {
            int m = i >> 7, kq = (i & 127) << 2;
            float4 v = __ldcg((const float4*)(hglob + m * HH + kq));
            uint32_t* d = s_h + m * REC_PAD + kq;
            d[0] = f2tf(v.x); d[1] = f2tf(v.y); d[2] = f2tf(v.z); d[3] = f2tf(v.w);
        }
        __syncthreads();

        float acc0[4] = {0.f, 0.f, 0.f, 0.f};
        float acc1[4] = {0.f, 0.f, 0.f, 0.f};
        const uint32_t* ab = s_h + (wm * 16) * REC_PAD;
#pragma unroll 8
        for (int kk = 0; kk < 64; kk++) {
            const uint32_t* ap = ab + kk * 8;
            uint32_t a[4];
            a[0] = ap[o0];     a[1] = ap[o1];
            a[2] = ap[o0 + 4]; a[3] = ap[o1 + 4];
            uint32_t b0[2], b1[2];
            *(uint2*)b0 = *(const uint2*)(b0base + kk * 64);
            *(uint2*)b1 = *(const uint2*)(b1base + kk * 64);
            mma_tf32(acc0, a, b0);
            mma_tf32(acc1, a, b1);
        }
        {
            int zr = wm * 16 + g;
            int zc = wn * 16 + tg * 2;
            *(float2*)&s_z[zr * 36 + zc]           = make_float2(acc0[0], acc0[1]);
            *(float2*)&s_z[(zr + 8) * 36 + zc]     = make_float2(acc0[2], acc0[3]);
            *(float2*)&s_z[zr * 36 + zc + 8]       = make_float2(acc1[0], acc1[1]);
            *(float2*)&s_z[(zr + 8) * 36 + zc + 8] = make_float2(acc1[2], acc1[3]);
        }
        __syncthreads();

        // gates: 2 elements per thread
#pragma unroll
        for (int half = 0; half < 2; half++) {
            int idx = tid + half * 256;
            int b = idx >> 3, u = idx & 7;
            const float* xp = xg + ((size_t)t * BB + b) * GG + hu0 + u;
            float zi = s_z[b * 36 + u]      + xp[0];
            float zf = s_z[b * 36 + 8 + u]  + xp[HH];
            float zg = s_z[b * 36 + 16 + u] + xp[2 * HH];
            float zo = s_z[b * 36 + 24 + u] + xp[3 * HH];
            float c  = s_c[idx];
            float cn = sigm(zf) * c + sigm(zi) * tanhf(zg);
            float hn = sigm(zo) * tanhf(cn);
            bool act = t < (half ? sl1 : sl0);
            if (act) { s_c[idx] = cn; hglob[b * HH + hu0 + u] = hn; }
            Hout[(size_t)(b * LL + t) * H2 + dir * HH + hu0 + u] = act ? hn : 0.f;
        }
        gsync_tree(blockIdx.x);
    }
}

// ---------------- epilogue -----------------------------------------------------
__global__ void k_docsum_part(const float* __restrict__ Hout,
                              const int* __restrict__ dlen, float* __restrict__ part)
{
    int b = blockIdx.x, c = blockIdx.y, tid = threadIdx.x;
    int dl = dlen[b];
    int t0 = c * 32, t1 = min(t0 + 32, dl);
    float acc[4] = {0.f, 0.f, 0.f, 0.f};
    for (int t = t0; t < t1; t++) {
        const float* hp = Hout + (size_t)(b * LL + t) * H2;
#pragma unroll
        for (int j = 0; j < 4; j++) acc[j] += hp[tid + j * 256];
    }
    float* pp = part + ((size_t)c * BB + b) * H2;
#pragma unroll
    for (int j = 0; j < 4; j++) pp[tid + j * 256] = acc[j];
}

__global__ void k_docsum_fin(const float* __restrict__ part,
                             const int* __restrict__ dlen, float* __restrict__ out)
{
    int b = blockIdx.x, tid = threadIdx.x;
    float inv = 1.f / (float)dlen[b];
    float acc[4] = {0.f, 0.f, 0.f, 0.f};
    for (int c = 0; c < 8; c++) {
        const float* pp = part + ((size_t)c * BB + b) * H2;
#pragma unroll
        for (int j = 0; j < 4; j++) acc[j] += pp[tid + j * 256];
    }
#pragma unroll
    for (int j = 0; j < 4; j++) out[b * H2 + tid + j * 256] = acc[j] * inv;
}

__global__ void k_mv(const float* __restrict__ W, const float* __restrict__ v,
                     const float* __restrict__ bias, float* __restrict__ out)
{
    int b = blockIdx.y;
    int wid = threadIdx.x >> 5, lane = threadIdx.x & 31;
    int d = blockIdx.x * 8 + wid;
    const float4* wp = (const float4*)(W + (size_t)d * H2);
    const float4* vp = (const float4*)(v + (size_t)b * H2);
    float acc = 0.f;
    for (int e = lane; e < H2 / 4; e += 32) {
        float4 a = wp[e], c = vp[e];
        acc += a.x * c.x + a.y * c.y + a.z * c.z + a.w * c.w;
    }
#pragma unroll
    for (int off = 16; off > 0; off >>= 1) acc += __shfl_down_sync(0xffffffffu, acc, off);
    if (lane == 0) out[b * H2 + d] = acc + (bias ? bias[d] : 0.f);
}

__global__ void k_base(const float* __restrict__ Hout, const float* __restrict__ S,
                       const float* __restrict__ w_con, const float* __restrict__ b_con,
                       const float* __restrict__ b_sal, const float* __restrict__ pos,
                       float* __restrict__ base)
{
    int b = blockIdx.x;
    int l = blockIdx.y * 8 + (threadIdx.x >> 5);
    int lane = threadIdx.x & 31;
    const float4* hp = (const float4*)(Hout + (size_t)(b * LL + l) * H2);
    const float4* wc = (const float4*)w_con;
    const float4* sp = (const float4*)(S + (size_t)b * H2);
    float a1 = 0.f, a2 = 0.f;
    for (int e = lane; e < H2 / 4; e += 32) {
        float4 h = hp[e], w = wc[e], s = sp[e];
        a1 += h.x * w.x + h.y * w.y + h.z * w.z + h.w * w.w;
        a2 += h.x * s.x + h.y * s.y + h.z * s.z + h.w * s.w;
    }
#pragma unroll
    for (int off = 16; off > 0; off >>= 1) {
        a1 += __shfl_down_sync(0xffffffffu, a1, off);
        a2 += __shfl_down_sync(0xffffffffu, a2, off);
    }
    if (lane == 0) base[b * LL + l] = a1 + a2 + b_con[0] + b_sal[0] + pos[l];
}

// one warp per batch row; running state register-resident; no block syncs
__global__ void k_scan(const float* __restrict__ Hout, const float* __restrict__ Hn,
                       const float* __restrict__ base, const float* __restrict__ b_nov,
                       const float* __restrict__ w_cls, const float* __restrict__ b_cls,
                       float* __restrict__ out)
{
    int b = blockIdx.x, lane = threadIdx.x;
    float4 s4[8];
#pragma unroll
    for (int j = 0; j < 8; j++) s4[j] = make_float4(0.f, 0.f, 0.f, 0.f);
    float wcls = w_cls[0], bcls = b_cls[0], bnov = b_nov[0];
    const float4* HnB = (const float4*)(Hn + (size_t)b * LL * H2);
    const float4* HoB = (const float4*)(Hout + (size_t)b * LL * H2);
    for (int i = 0; i < LL; i++) {
        const float4* hn = HnB + (size_t)i * 256 + lane * 8;
        float part = 0.f;
#pragma unroll
        for (int j = 0; j < 8; j++) {
            float4 h = hn[j];
            part += h.x * s4[j].x + h.y * s4[j].y + h.z * s4[j].z + h.w * s4[j].w;
        }
#pragma unroll
        for (int off = 16; off > 0; off >>= 1) part += __shfl_xor_sync(0xffffffffu, part, off);
        float nov = (i == 0) ? 0.f : (part + bnov);
        float p = sigm(wcls * (base[b * LL + i] + nov) + bcls);
        const float4* ho = HoB + (size_t)i * 256 + lane * 8;
#pragma unroll
        for (int j = 0; j < 8; j++) {
            float4 h = ho[j];
            s4[j].x += h.x * p; s4[j].y += h.y * p;
            s4[j].z += h.z * p; s4[j].w += h.w * p;
        }
        if (lane == 0) out[b * LL + i] = p;
    }
}

// ---------------- launch --------------------------------------------------------
extern "C" void kernel_launch(void* const* d_in, const int* in_sizes, int n_in,
                              void* d_out, int out_size)
{
    (void)in_sizes; (void)n_in; (void)out_size;
    const float* x     = (const float*)d_in[0];
    const int*   slen  = (const int*)  d_in[1];
    const int*   dlen  = (const int*)  d_in[2];
    const float* Wih_f = (const float*)d_in[3];
    const float* Whh_f = (const float*)d_in[4];
    const float* b_f   = (const float*)d_in[5];
    const float* Wih_b = (const float*)d_in[6];
    const float* Whh_b = (const float*)d_in[7];
    const float* b_b   = (const float*)d_in[8];
    const float* W_doc = (const float*)d_in[9];
    const float* b_doc = (const float*)d_in[10];
    const float* w_con = (const float*)d_in[11];
    const float* b_con = (const float*)d_in[12];
    const float* W_sal = (const float*)d_in[13];
    const float* b_sal = (const float*)d_in[14];
    const float* W_nov = (const float*)d_in[15];
    const float* b_nov = (const float*)d_in[16];
    const float* pos   = (const float*)d_in[17];
    const float* w_cls = (const float*)d_in[18];
    const float* b_cls = (const float*)d_in[19];
    float* out = (float*)d_out;

    float *p_xg0, *p_xg1, *p_Hout, *p_Hn, *p_WnT, *p_hbuf, *p_part, *p_doc, *p_D, *p_S, *p_base;
    cudaGetSymbolAddress((void**)&p_xg0,  g_xg0);
    cudaGetSymbolAddress((void**)&p_xg1,  g_xg1);
    cudaGetSymbolAddress((void**)&p_Hout, g_Hout);
    cudaGetSymbolAddress((void**)&p_Hn,   g_Hn);
    cudaGetSymbolAddress((void**)&p_WnT,  g_WnT);
    cudaGetSymbolAddress((void**)&p_hbuf, g_hbuf);
    cudaGetSymbolAddress((void**)&p_part, g_docpart);
    cudaGetSymbolAddress((void**)&p_doc,  g_doc);
    cudaGetSymbolAddress((void**)&p_D,    g_D);
    cudaGetSymbolAddress((void**)&p_S,    g_S);
    cudaGetSymbolAddress((void**)&p_base, g_base);

    const int M = BB * LL;

    k_gemm_tf32<true><<<dim3(GG / 128, M / 128), 256>>>(x, Wih_f, b_f, p_xg0, M, GG, EE);
    k_gemm_tf32<true><<<dim3(GG / 128, M / 128), 256>>>(x, Wih_b, b_b, p_xg1, M, GG, EE);
    k_transpose<<<dim3(32, 32), dim3(32, 8)>>>(W_nov, p_WnT);

    const int REC_SMEM = (64 * REC_PAD + 16384 + 64 * 36 + 512) * 4;
    cudaFuncSetAttribute(k_recurrent, cudaFuncAttributeMaxDynamicSharedMemorySize, REC_SMEM);
    k_recurrent<<<128, 256, REC_SMEM>>>(Whh_f, Whh_b, slen, p_xg0, p_xg1, p_hbuf, p_Hout);

    k_docsum_part<<<dim3(BB, 8), 256>>>(p_Hout, dlen, p_part);
    k_docsum_fin<<<BB, 256>>>(p_part, dlen, p_doc);
    k_mv<<<dim3(H2 / 8, BB), 256>>>(W_doc, p_doc, b_doc, p_D);
    k_mv<<<dim3(H2 / 8, BB), 256>>>(W_sal, p_D, nullptr, p_S);

    k_gemm_tf32<false><<<dim3(H2 / 128, M / 128), 256>>>(p_Hout, p_WnT, nullptr, p_Hn, M, H2, H2);

    k_base<<<dim3(BB, LL / 8), 256>>>(p_Hout, p_S, w_con, b_con, b_sal, pos, p_base);
    k_scan<<<BB, 32>>>(p_Hout, p_Hn, p_base, b_nov, w_cls, b_cls, out);
}

// round 4
// speedup vs baseline: 2.5969x; 1.2953x over previous
#include <cuda_runtime.h>
#include <cuda_bf16.h>
#include <math.h>
#include <stdint.h>

#define BB 64
#define LL 256
#define EE 512
#define HH 512
#define GG 2048   // 4*H
#define H2 1024   // 2*H
#define REC_PAD 516
#define ZPAD 80

// ---------------- scratch (device globals; no allocations allowed) -------------
__device__ float g_xg0[LL * BB * GG];
__device__ float g_xg1[LL * BB * GG];
__device__ float g_Hout[BB * LL * H2];
__device__ float g_Hn[BB * LL * H2];
__device__ float g_WnT[H2 * H2];
__device__ float g_hbuf[2 * BB * HH];
__device__ float g_docpart[8 * BB * H2];
__device__ float g_doc[BB * H2];
__device__ float g_D[BB * H2];
__device__ float g_S[BB * H2];
__device__ float g_base[BB * LL];
__device__ unsigned g_cnt[4 * 32];   // 4 groups, 128B apart
__device__ unsigned g_gen[4 * 32];

// ---------------- per-group barrier (32 CTAs each, replay-safe) ----------------
__device__ __forceinline__ void gsync_grp(int grp) {
    __syncthreads();
    if (threadIdx.x == 0) {
        __threadfence();
        volatile unsigned* gen = &g_gen[grp * 32];
        unsigned old = *gen;
        if (atomicInc(&g_cnt[grp * 32], 31u) == 31u) {   // wraps to 0
            atomicAdd(&g_gen[grp * 32], 1u);
        } else {
            while (*gen == old) __nanosleep(32);
        }
    }
    __syncthreads();
}

__device__ __forceinline__ float sigm(float x) { return 1.f / (1.f + __expf(-x)); }

__device__ __forceinline__ uint32_t f2tf(float f) {
    uint32_t u; asm("cvt.rna.tf32.f32 %0, %1;" : "=r"(u) : "f"(f)); return u;
}

__device__ __forceinline__ void mma_tf32(float* c, const uint32_t* a, const uint32_t* b) {
    asm volatile(
        "mma.sync.aligned.m16n8k8.row.col.f32.tf32.tf32.f32 "
        "{%0,%1,%2,%3}, {%4,%5,%6,%7}, {%8,%9}, {%0,%1,%2,%3};"
        : "+f"(c[0]), "+f"(c[1]), "+f"(c[2]), "+f"(c[3])
        : "r"(a[0]), "r"(a[1]), "r"(a[2]), "r"(a[3]), "r"(b[0]), "r"(b[1]));
}

// ---------------- tf32 tensor-core GEMM (validated R2/R3) ----------------------
template <bool REMAP>
__global__ __launch_bounds__(256, 2) void k_gemm_tf32(
    const float* __restrict__ A, const float* __restrict__ Bt,
    const float* __restrict__ bias, float* __restrict__ C,
    int M, int N, int K)
{
    __shared__ uint32_t As[128 * 36];
    __shared__ uint32_t Bs[128 * 36];
    const int tid = threadIdx.x;
    const int lane = tid & 31;
    const int warp = tid >> 5;
    const int wm = warp >> 2;
    const int wn = warp & 3;
    const int g  = lane >> 2;
    const int tg = lane & 3;
    const int bm = blockIdx.y * 128;
    const int bn = blockIdx.x * 128;
    const int srow = tid >> 3;
    const int scol = (tid & 7) << 2;

    float acc[4][4][4];
#pragma unroll
    for (int i = 0; i < 4; i++)
#pragma unroll
        for (int j = 0; j < 4; j++)
#pragma unroll
            for (int e = 0; e < 4; e++) acc[i][j][e] = 0.f;

    for (int k0 = 0; k0 < K; k0 += 32) {
#pragma unroll
        for (int r = 0; r < 4; r++) {
            int row = srow + 32 * r;
            float4 va = *(const float4*)(A + (size_t)(bm + row) * K + k0 + scol);
            uint32_t* ap = &As[row * 36 + scol];
            ap[0] = f2tf(va.x); ap[1] = f2tf(va.y); ap[2] = f2tf(va.z); ap[3] = f2tf(va.w);
            float4 vb = *(const float4*)(Bt + (size_t)(bn + row) * K + k0 + scol);
            uint32_t* bp = &Bs[row * 36 + scol];
            bp[0] = f2tf(vb.x); bp[1] = f2tf(vb.y); bp[2] = f2tf(vb.z); bp[3] = f2tf(vb.w);
        }
        __syncthreads();
#pragma unroll
        for (int kk = 0; kk < 32; kk += 8) {
            uint32_t a[4][4], b[4][2];
#pragma unroll
            for (int i = 0; i < 4; i++) {
                int base = wm * 64 + i * 16;
                a[i][0] = As[(base + g)     * 36 + kk + tg];
                a[i][1] = As[(base + g + 8) * 36 + kk + tg];
                a[i][2] = As[(base + g)     * 36 + kk + tg + 4];
                a[i][3] = As[(base + g + 8) * 36 + kk + tg + 4];
            }
#pragma unroll
            for (int j = 0; j < 4; j++) {
                int nb = wn * 32 + j * 8;
                b[j][0] = Bs[(nb + g) * 36 + kk + tg];
                b[j][1] = Bs[(nb + g) * 36 + kk + tg + 4];
            }
#pragma unroll
            for (int i = 0; i < 4; i++)
#pragma unroll
                for (int j = 0; j < 4; j++) mma_tf32(acc[i][j], a[i], b[j]);
        }
        __syncthreads();
    }
#pragma unroll
    for (int i = 0; i < 4; i++) {
#pragma unroll
        for (int j = 0; j < 4; j++) {
            int col = bn + wn * 32 + j * 8 + tg * 2;
            float bv0 = bias ? bias[col] : 0.f;
            float bv1 = bias ? bias[col + 1] : 0.f;
            int m0 = bm + wm * 64 + i * 16 + g;
            int m1 = m0 + 8;
            int r0 = REMAP ? ((m0 & (LL - 1)) * BB + (m0 >> 8)) : m0;
            int r1 = REMAP ? ((m1 & (LL - 1)) * BB + (m1 >> 8)) : m1;
            *(float2*)(C + (size_t)r0 * N + col) = make_float2(acc[i][j][0] + bv0, acc[i][j][1] + bv1);
            *(float2*)(C + (size_t)r1 * N + col) = make_float2(acc[i][j][2] + bv0, acc[i][j][3] + bv1);
        }
    }
}

// ---------------- 1024x1024 transpose ------------------------------------------
__global__ void k_transpose(const float* __restrict__ in, float* __restrict__ out) {
    __shared__ float t[32][33];
    int bx = blockIdx.x * 32, by = blockIdx.y * 32;
    int x = threadIdx.x, y = threadIdx.y;
#pragma unroll
    for (int j = 0; j < 32; j += 8) t[y + j][x] = in[(size_t)(by + y + j) * H2 + bx + x];
    __syncthreads();
#pragma unroll
    for (int j = 0; j < 32; j += 8) out[(size_t)(bx + y + j) * H2 + by + x] = t[x][y + j];
}

// ---------------- persistent bidirectional LSTM, tf32 mma ----------------------
// 128 CTAs = (dir, batch-group bg in {0,1}, unit-seg in {0..31}).
// Each CTA: 16 units x 4 gates x 32 batch rows. z[32,64] = h[32,512] @ W[64,512]^T.
// Barrier groups: (dir,bg) -> 4 independent groups of 32 CTAs.
__global__ __launch_bounds__(256, 1) void k_recurrent(
    const float* __restrict__ Whh_f, const float* __restrict__ Whh_b,
    const int* __restrict__ slen,
    const float* __restrict__ xg0, const float* __restrict__ xg1,
    float* __restrict__ hbuf, float* __restrict__ Hout)
{
    extern __shared__ float sm[];
    uint32_t* s_h  = (uint32_t*)sm;                       // [32][516] tf32
    uint32_t* s_wf = (uint32_t*)sm + 32 * REC_PAD;        // [8][64][32][2] frag-major
    float* s_z = sm + 32 * REC_PAD + 32768;               // [32][80]
    float* s_c = s_z + 32 * ZPAD;                         // [512]

    const int tid = threadIdx.x;
    const int lane = tid & 31;
    const int warp = tid >> 5;
    const int wm = warp >> 2;           // 0..1 -> batch rows wm*16..+15
    const int wn = warp & 3;            // 0..3 -> gate-col slab wn*16..+15
    const int g  = lane >> 2;
    const int tg = lane & 3;
    const int dir = blockIdx.x >> 6;
    const int bg  = (blockIdx.x >> 5) & 1;
    const int useg = blockIdx.x & 31;
    const int hu0 = useg * 16;
    const int grp = blockIdx.x >> 5;    // dir*2 + bg
    const float* Whh = dir ? Whh_b : Whh_f;
    const float* xg  = dir ? xg1 : xg0;
    float* hglob = hbuf + dir * (BB * HH);
    const float* hsrc = hglob + bg * 32 * HH;

    // one-time: pack Whh fragments (tf32, frag-major). n = gate*16 + unit_local.
    for (int s = tid; s < 32768; s += 256) {
        int reg = s & 1;
        int l   = (s >> 1) & 31;
        int kk  = (s >> 6) & 63;
        int fi  = s >> 12;                 // wn*2 + j
        int n   = (fi >> 1) * 16 + (fi & 1) * 8 + (l >> 2);
        int k   = kk * 8 + (l & 3) + reg * 4;
        int gate = n >> 4, unit = hu0 + (n & 15);
        s_wf[s] = f2tf(Whh[(size_t)(gate * HH + unit) * HH + k]);
    }
    for (int i = tid; i < 512; i += 256) s_c[i] = 0.f;
    // zero our slice of h
#pragma unroll
    for (int half = 0; half < 2; half++) {
        int idx = tid + half * 256;
        int b = bg * 32 + (idx >> 4), u = idx & 15;
        hglob[b * HH + hu0 + u] = 0.f;
    }
    gsync_grp(grp);

    const int sl0 = slen[bg * 32 + (tid >> 4)];
    const int sl1 = slen[bg * 32 + 16 + (tid >> 4)];

    const int o0 = g * REC_PAD + tg;
    const int o1 = o0 + 8 * REC_PAD;
    const uint32_t* b0base = s_wf + (wn * 2) * 4096 + lane * 2;
    const uint32_t* b1base = b0base + 4096;

    for (int step = 0; step < LL; ++step) {
        const int t = dir ? (LL - 1 - step) : step;

        // prefetch xg for both halves (consumed after mma)
        float x0[4], x1[4];
        {
            const float* xp0 = xg + ((size_t)t * BB + bg * 32 + (tid >> 4)) * GG + hu0 + (tid & 15);
            x0[0] = xp0[0]; x0[1] = xp0[HH]; x0[2] = xp0[2 * HH]; x0[3] = xp0[3 * HH];
            const float* xp1 = xp0 + 16 * GG;
            x1[0] = xp1[0]; x1[1] = xp1[HH]; x1[2] = xp1[2 * HH]; x1[3] = xp1[3 * HH];
        }

        // stage our 32 h rows -> smem tf32 (contiguous 64KB, L2 reads)
        for (int i = tid; i < 4096; i += 256) {
            int m = i >> 7, kq = (i & 127) << 2;
            float4 v = __ldcg((const float4*)(hsrc + m * HH + kq));
            uint32_t* d = s_h + m * REC_PAD + kq;
            d[0] = f2tf(v.x); d[1] = f2tf(v.y); d[2] = f2tf(v.z); d[3] = f2tf(v.w);
        }
        __syncthreads();

        float acc0[4] = {0.f, 0.f, 0.f, 0.f};
        float acc1[4] = {0.f, 0.f, 0.f, 0.f};
        const uint32_t* ab = s_h + (wm * 16) * REC_PAD;
#pragma unroll 8
        for (int kk = 0; kk < 64; kk++) {
            const uint32_t* ap = ab + kk * 8;
            uint32_t a[4];
            a[0] = ap[o0];     a[1] = ap[o1];
            a[2] = ap[o0 + 4]; a[3] = ap[o1 + 4];
            uint32_t b0[2], b1[2];
            *(uint2*)b0 = *(const uint2*)(b0base + kk * 64);
            *(uint2*)b1 = *(const uint2*)(b1base + kk * 64);
            mma_tf32(acc0, a, b0);
            mma_tf32(acc1, a, b1);
        }
        {
            int zr = wm * 16 + g;
            int zc = wn * 16 + tg * 2;
            *(float2*)&s_z[zr * ZPAD + zc]           = make_float2(acc0[0], acc0[1]);
            *(float2*)&s_z[(zr + 8) * ZPAD + zc]     = make_float2(acc0[2], acc0[3]);
            *(float2*)&s_z[zr * ZPAD + zc + 8]       = make_float2(acc1[0], acc1[1]);
            *(float2*)&s_z[(zr + 8) * ZPAD + zc + 8] = make_float2(acc1[2], acc1[3]);
        }
        __syncthreads();

        // gates: 2 elements per thread (u = unit_local, n = gate*16 + u)
#pragma unroll
        for (int half = 0; half < 2; half++) {
            int idx = tid + half * 256;
            int bl = idx >> 4, u = idx & 15;
            int b = bg * 32 + bl;
            const float* xv = half ? x1 : x0;
            float zi = s_z[bl * ZPAD + u]      + xv[0];
            float zf = s_z[bl * ZPAD + 16 + u] + xv[1];
            float zg = s_z[bl * ZPAD + 32 + u] + xv[2];
            float zo = s_z[bl * ZPAD + 48 + u] + xv[3];
            float c  = s_c[idx];
            float cn = sigm(zf) * c + sigm(zi) * tanhf(zg);
            float hn = sigm(zo) * tanhf(cn);
            bool act = t < (half ? sl1 : sl0);
            if (act) { s_c[idx] = cn; hglob[b * HH + hu0 + u] = hn; }
            Hout[(size_t)(b * LL + t) * H2 + dir * HH + hu0 + u] = act ? hn : 0.f;
        }
        gsync_grp(grp);
    }
}

// ---------------- epilogue -----------------------------------------------------
__global__ void k_docsum_part(const float* __restrict__ Hout,
                              const int* __restrict__ dlen, float* __restrict__ part)
{
    int b = blockIdx.x, c = blockIdx.y, tid = threadIdx.x;
    int dl = dlen[b];
    int t0 = c * 32, t1 = min(t0 + 32, dl);
    float acc[4] = {0.f, 0.f, 0.f, 0.f};
    for (int t = t0; t < t1; t++) {
        const float* hp = Hout + (size_t)(b * LL + t) * H2;
#pragma unroll
        for (int j = 0; j < 4; j++) acc[j] += hp[tid + j * 256];
    }
    float* pp = part + ((size_t)c * BB + b) * H2;
#pragma unroll
    for (int j = 0; j < 4; j++) pp[tid + j * 256] = acc[j];
}

__global__ void k_docsum_fin(const float* __restrict__ part,
                             const int* __restrict__ dlen, float* __restrict__ out)
{
    int b = blockIdx.x, tid = threadIdx.x;
    float inv = 1.f / (float)dlen[b];
    float acc[4] = {0.f, 0.f, 0.f, 0.f};
    for (int c = 0; c < 8; c++) {
        const float* pp = part + ((size_t)c * BB + b) * H2;
#pragma unroll
        for (int j = 0; j < 4; j++) acc[j] += pp[tid + j * 256];
    }
#pragma unroll
    for (int j = 0; j < 4; j++) out[b * H2 + tid + j * 256] = acc[j] * inv;
}

__global__ void k_mv(const float* __restrict__ W, const float* __restrict__ v,
                     const float* __restrict__ bias, float* __restrict__ out)
{
    int b = blockIdx.y;
    int wid = threadIdx.x >> 5, lane = threadIdx.x & 31;
    int d = blockIdx.x * 8 + wid;
    const float4* wp = (const float4*)(W + (size_t)d * H2);
    const float4* vp = (const float4*)(v + (size_t)b * H2);
    float acc = 0.f;
    for (int e = lane; e < H2 / 4; e += 32) {
        float4 a = wp[e], c = vp[e];
        acc += a.x * c.x + a.y * c.y + a.z * c.z + a.w * c.w;
    }
#pragma unroll
    for (int off = 16; off > 0; off >>= 1) acc += __shfl_down_sync(0xffffffffu, acc, off);
    if (lane == 0) out[b * H2 + d] = acc + (bias ? bias[d] : 0.f);
}

__global__ void k_base(const float* __restrict__ Hout, const float* __restrict__ S,
                       const float* __restrict__ w_con, const float* __restrict__ b_con,
                       const float* __restrict__ b_sal, const float* __restrict__ pos,
                       float* __restrict__ base)
{
    int b = blockIdx.x;
    int l = blockIdx.y * 8 + (threadIdx.x >> 5);
    int lane = threadIdx.x & 31;
    const float4* hp = (const float4*)(Hout + (size_t)(b * LL + l) * H2);
    const float4* wc = (const float4*)w_con;
    const float4* sp = (const float4*)(S + (size_t)b * H2);
    float a1 = 0.f, a2 = 0.f;
    for (int e = lane; e < H2 / 4; e += 32) {
        float4 h = hp[e], w = wc[e], s = sp[e];
        a1 += h.x * w.x + h.y * w.y + h.z * w.z + h.w * w.w;
        a2 += h.x * s.x + h.y * s.y + h.z * s.z + h.w * s.w;
    }
#pragma unroll
    for (int off = 16; off > 0; off >>= 1) {
        a1 += __shfl_down_sync(0xffffffffu, a1, off);
        a2 += __shfl_down_sync(0xffffffffu, a2, off);
    }
    if (lane == 0) base[b * LL + l] = a1 + a2 + b_con[0] + b_sal[0] + pos[l];
}

__global__ void k_scan(const float* __restrict__ Hout, const float* __restrict__ Hn,
                       const float* __restrict__ base, const float* __restrict__ b_nov,
                       const float* __restrict__ w_cls, const float* __restrict__ b_cls,
                       float* __restrict__ out)
{
    int b = blockIdx.x, lane = threadIdx.x;
    float4 s4[8];
#pragma unroll
    for (int j = 0; j < 8; j++) s4[j] = make_float4(0.f, 0.f, 0.f, 0.f);
    float wcls = w_cls[0], bcls = b_cls[0], bnov = b_nov[0];
    const float4* HnB = (const float4*)(Hn + (size_t)b * LL * H2);
    const float4* HoB = (const float4*)(Hout + (size_t)b * LL * H2);
    for (int i = 0; i < LL; i++) {
        const float4* hn = HnB + (size_t)i * 256 + lane * 8;
        float part = 0.f;
#pragma unroll
        for (int j = 0; j < 8; j++) {
            float4 h = hn[j];
            part += h.x * s4[j].x + h.y * s4[j].y + h.z * s4[j].z + h.w * s4[j].w;
        }
#pragma unroll
        for (int off = 16; off > 0; off >>= 1) part += __shfl_xor_sync(0xffffffffu, part, off);
        float nov = (i == 0) ? 0.f : (part + bnov);
        float p = sigm(wcls * (base[b * LL + i] + nov) + bcls);
        const float4* ho = HoB + (size_t)i * 256 + lane * 8;
#pragma unroll
        for (int j = 0; j < 8; j++) {
            float4 h = ho[j];
            s4[j].x += h.x * p; s4[j].y += h.y * p;
            s4[j].z += h.z * p; s4[j].w += h.w * p;
        }
        if (lane == 0) out[b * LL + i] = p;
    }
}

// ---------------- launch --------------------------------------------------------
extern "C" void kernel_launch(void* const* d_in, const int* in_sizes, int n_in,
                              void* d_out, int out_size)
{
    (void)in_sizes; (void)n_in; (void)out_size;
    const float* x     = (const float*)d_in[0];
    const int*   slen  = (const int*)  d_in[1];
    const int*   dlen  = (const int*)  d_in[2];
    const float* Wih_f = (const float*)d_in[3];
    const float* Whh_f = (const float*)d_in[4];
    const float* b_f   = (const float*)d_in[5];
    const float* Wih_b = (const float*)d_in[6];
    const float* Whh_b = (const float*)d_in[7];
    const float* b_b   = (const float*)d_in[8];
    const float* W_doc = (const float*)d_in[9];
    const float* b_doc = (const float*)d_in[10];
    const float* w_con = (const float*)d_in[11];
    const float* b_con = (const float*)d_in[12];
    const float* W_sal = (const float*)d_in[13];
    const float* b_sal = (const float*)d_in[14];
    const float* W_nov = (const float*)d_in[15];
    const float* b_nov = (const float*)d_in[16];
    const float* pos   = (const float*)d_in[17];
    const float* w_cls = (const float*)d_in[18];
    const float* b_cls = (const float*)d_in[19];
    float* out = (float*)d_out;

    float *p_xg0, *p_xg1, *p_Hout, *p_Hn, *p_WnT, *p_hbuf, *p_part, *p_doc, *p_D, *p_S, *p_base;
    cudaGetSymbolAddress((void**)&p_xg0,  g_xg0);
    cudaGetSymbolAddress((void**)&p_xg1,  g_xg1);
    cudaGetSymbolAddress((void**)&p_Hout, g_Hout);
    cudaGetSymbolAddress((void**)&p_Hn,   g_Hn);
    cudaGetSymbolAddress((void**)&p_WnT,  g_WnT);
    cudaGetSymbolAddress((void**)&p_hbuf, g_hbuf);
    cudaGetSymbolAddress((void**)&p_part, g_docpart);
    cudaGetSymbolAddress((void**)&p_doc,  g_doc);
    cudaGetSymbolAddress((void**)&p_D,    g_D);
    cudaGetSymbolAddress((void**)&p_S,    g_S);
    cudaGetSymbolAddress((void**)&p_base, g_base);

    const int M = BB * LL;

    k_gemm_tf32<true><<<dim3(GG / 128, M / 128), 256>>>(x, Wih_f, b_f, p_xg0, M, GG, EE);
    k_gemm_tf32<true><<<dim3(GG / 128, M / 128), 256>>>(x, Wih_b, b_b, p_xg1, M, GG, EE);
    k_transpose<<<dim3(32, 32), dim3(32, 8)>>>(W_nov, p_WnT);

    const int REC_SMEM = (32 * REC_PAD + 32768 + 32 * ZPAD + 512) * 4;
    cudaFuncSetAttribute(k_recurrent, cudaFuncAttributeMaxDynamicSharedMemorySize, REC_SMEM);
    k_recurrent<<<128, 256, REC_SMEM>>>(Whh_f, Whh_b, slen, p_xg0, p_xg1, p_hbuf, p_Hout);

    k_docsum_part<<<dim3(BB, 8), 256>>>(p_Hout, dlen, p_part);
    k_docsum_fin<<<BB, 256>>>(p_part, dlen, p_doc);
    k_mv<<<dim3(H2 / 8, BB), 256>>>(W_doc, p_doc, b_doc, p_D);
    k_mv<<<dim3(H2 / 8, BB), 256>>>(W_sal, p_D, nullptr, p_S);

    k_gemm_tf32<false><<<dim3(H2 / 128, M / 128), 256>>>(p_Hout, p_WnT, nullptr, p_Hn, M, H2, H2);

    k_base<<<dim3(BB, LL / 8), 256>>>(p_Hout, p_S, w_con, b_con, b_sal, pos, p_base);
    k_scan<<<BB, 32>>>(p_Hout, p_Hn, p_base, b_nov, w_cls, b_cls, out);
}

// round 5
// speedup vs baseline: 2.8482x; 1.0968x over previous
#include <cuda_runtime.h>
#include <cuda_bf16.h>
#include <math.h>
#include <stdint.h>

#define BB 64
#define LL 256
#define EE 512
#define HH 512
#define GG 2048   // 4*H
#define H2 1024   // 2*H
#define REC_PAD 516
#define ZPAD 80

// ---------------- scratch (device globals; no allocations allowed) -------------
__device__ float g_xg0[LL * BB * GG];
__device__ float g_xg1[LL * BB * GG];
__device__ float g_Hout[BB * LL * H2];
__device__ float g_Hn[BB * LL * H2];
__device__ float g_WnT[H2 * H2];
__device__ float g_hbuf[2 * BB * HH];     // holds tf32 bit patterns
__device__ float g_docpart[8 * BB * H2];
__device__ float g_doc[BB * H2];
__device__ float g_D[BB * H2];
__device__ float g_S[BB * H2];
__device__ float g_base[BB * LL];
__device__ unsigned g_cnt[4 * 32];   // 4 groups, 128B apart
__device__ unsigned g_gen[4 * 32];

// ---------------- per-group barrier (32 CTAs each, replay-safe) ----------------
__device__ __forceinline__ void gsync_grp(int grp) {
    __syncthreads();
    if (threadIdx.x == 0) {
        __threadfence();
        volatile unsigned* gen = &g_gen[grp * 32];
        unsigned old = *gen;
        if (atomicInc(&g_cnt[grp * 32], 31u) == 31u) {   // wraps to 0
            atomicAdd(&g_gen[grp * 32], 1u);
        } else {
            while (*gen == old) __nanosleep(32);
        }
    }
    __syncthreads();
}

// fast MUFU.TANH nonlinearities
__device__ __forceinline__ float tanha(float x) {
    float r; asm("tanh.approx.f32 %0, %1;" : "=f"(r) : "f"(x)); return r;
}
__device__ __forceinline__ float sigm_fast(float x) {
    return fmaf(tanha(0.5f * x), 0.5f, 0.5f);
}

__device__ __forceinline__ uint32_t f2tf(float f) {
    uint32_t u; asm("cvt.rna.tf32.f32 %0, %1;" : "=r"(u) : "f"(f)); return u;
}

__device__ __forceinline__ void mma_tf32(float* c, const uint32_t* a, const uint32_t* b) {
    asm volatile(
        "mma.sync.aligned.m16n8k8.row.col.f32.tf32.tf32.f32 "
        "{%0,%1,%2,%3}, {%4,%5,%6,%7}, {%8,%9}, {%0,%1,%2,%3};"
        : "+f"(c[0]), "+f"(c[1]), "+f"(c[2]), "+f"(c[3])
        : "r"(a[0]), "r"(a[1]), "r"(a[2]), "r"(a[3]), "r"(b[0]), "r"(b[1]));
}

// ---------------- tf32 tensor-core GEMM with A-register prefetch ---------------
template <bool REMAP>
__global__ __launch_bounds__(256, 2) void k_gemm_tf32(
    const float* __restrict__ A, const float* __restrict__ Bt,
    const float* __restrict__ bias, float* __restrict__ C,
    int M, int N, int K)
{
    __shared__ uint32_t As[128 * 36];
    __shared__ uint32_t Bs[128 * 36];
    const int tid = threadIdx.x;
    const int lane = tid & 31;
    const int warp = tid >> 5;
    const int wm = warp >> 2;
    const int wn = warp & 3;
    const int g  = lane >> 2;
    const int tg = lane & 3;
    const int bm = blockIdx.y * 128;
    const int bn = blockIdx.x * 128;
    const int srow = tid >> 3;
    const int scol = (tid & 7) << 2;

    float acc[4][4][4];
#pragma unroll
    for (int i = 0; i < 4; i++)
#pragma unroll
        for (int j = 0; j < 4; j++)
#pragma unroll
            for (int e = 0; e < 4; e++) acc[i][j][e] = 0.f;

    // prologue: prefetch A tile 0
    float4 va[4];
#pragma unroll
    for (int r = 0; r < 4; r++)
        va[r] = *(const float4*)(A + (size_t)(bm + srow + 32 * r) * K + scol);

    for (int k0 = 0; k0 < K; k0 += 32) {
#pragma unroll
        for (int r = 0; r < 4; r++) {
            int row = srow + 32 * r;
            uint32_t* ap = &As[row * 36 + scol];
            ap[0] = f2tf(va[r].x); ap[1] = f2tf(va[r].y);
            ap[2] = f2tf(va[r].z); ap[3] = f2tf(va[r].w);
            float4 vb = *(const float4*)(Bt + (size_t)(bn + row) * K + k0 + scol);
            uint32_t* bp = &Bs[row * 36 + scol];
            bp[0] = f2tf(vb.x); bp[1] = f2tf(vb.y); bp[2] = f2tf(vb.z); bp[3] = f2tf(vb.w);
        }
        __syncthreads();

        if (k0 + 32 < K) {   // prefetch next A tile; overlaps with mma below
#pragma unroll
            for (int r = 0; r < 4; r++)
                va[r] = *(const float4*)(A + (size_t)(bm + srow + 32 * r) * K + k0 + 32 + scol);
        }

#pragma unroll
        for (int kk = 0; kk < 32; kk += 8) {
            uint32_t a[4][4], b[4][2];
#pragma unroll
            for (int i = 0; i < 4; i++) {
                int base = wm * 64 + i * 16;
                a[i][0] = As[(base + g)     * 36 + kk + tg];
                a[i][1] = As[(base + g + 8) * 36 + kk + tg];
                a[i][2] = As[(base + g)     * 36 + kk + tg + 4];
                a[i][3] = As[(base + g + 8) * 36 + kk + tg + 4];
            }
#pragma unroll
            for (int j = 0; j < 4; j++) {
                int nb = wn * 32 + j * 8;
                b[j][0] = Bs[(nb + g) * 36 + kk + tg];
                b[j][1] = Bs[(nb + g) * 36 + kk + tg + 4];
            }
#pragma unroll
            for (int i = 0; i < 4; i++)
#pragma unroll
                for (int j = 0; j < 4; j++) mma_tf32(acc[i][j], a[i], b[j]);
        }
        __syncthreads();
    }
#pragma unroll
    for (int i = 0; i < 4; i++) {
#pragma unroll
        for (int j = 0; j < 4; j++) {
            int col = bn + wn * 32 + j * 8 + tg * 2;
            float bv0 = bias ? bias[col] : 0.f;
            float bv1 = bias ? bias[col + 1] : 0.f;
            int m0 = bm + wm * 64 + i * 16 + g;
            int m1 = m0 + 8;
            int r0 = REMAP ? ((m0 & (LL - 1)) * BB + (m0 >> 8)) : m0;
            int r1 = REMAP ? ((m1 & (LL - 1)) * BB + (m1 >> 8)) : m1;
            *(float2*)(C + (size_t)r0 * N + col) = make_float2(acc[i][j][0] + bv0, acc[i][j][1] + bv1);
            *(float2*)(C + (size_t)r1 * N + col) = make_float2(acc[i][j][2] + bv0, acc[i][j][3] + bv1);
        }
    }
}

// ---------------- 1024x1024 transpose ------------------------------------------
__global__ void k_transpose(const float* __restrict__ in, float* __restrict__ out) {
    __shared__ float t[32][33];
    int bx = blockIdx.x * 32, by = blockIdx.y * 32;
    int x = threadIdx.x, y = threadIdx.y;
#pragma unroll
    for (int j = 0; j < 32; j += 8) t[y + j][x] = in[(size_t)(by + y + j) * H2 + bx + x];
    __syncthreads();
#pragma unroll
    for (int j = 0; j < 32; j += 8) out[(size_t)(bx + y + j) * H2 + by + x] = t[x][y + j];
}

// ---------------- persistent bidirectional LSTM, tf32 mma ----------------------
// 128 CTAs = (dir, batch-group bg in {0,1}, unit-seg in {0..31}).
// hbuf holds tf32 bit patterns (converted once at production).
__global__ __launch_bounds__(256, 1) void k_recurrent(
    const float* __restrict__ Whh_f, const float* __restrict__ Whh_b,
    const int* __restrict__ slen,
    const float* __restrict__ xg0, const float* __restrict__ xg1,
    float* __restrict__ hbuf, float* __restrict__ Hout)
{
    extern __shared__ float sm[];
    uint32_t* s_h  = (uint32_t*)sm;                       // [32][516] tf32
    uint32_t* s_wf = (uint32_t*)sm + 32 * REC_PAD;        // [8][64][32][2] frag-major
    float* s_z = sm + 32 * REC_PAD + 32768;               // [32][80]
    float* s_c = s_z + 32 * ZPAD;                         // [512]

    const int tid = threadIdx.x;
    const int lane = tid & 31;
    const int warp = tid >> 5;
    const int wm = warp >> 2;
    const int wn = warp & 3;
    const int g  = lane >> 2;
    const int tg = lane & 3;
    const int dir = blockIdx.x >> 6;
    const int bg  = (blockIdx.x >> 5) & 1;
    const int useg = blockIdx.x & 31;
    const int hu0 = useg * 16;
    const int grp = blockIdx.x >> 5;
    const float* Whh = dir ? Whh_b : Whh_f;
    const float* xg  = dir ? xg1 : xg0;
    float* hglob = hbuf + dir * (BB * HH);
    const float* hsrc = hglob + bg * 32 * HH;

    for (int s = tid; s < 32768; s += 256) {
        int reg = s & 1;
        int l   = (s >> 1) & 31;
        int kk  = (s >> 6) & 63;
        int fi  = s >> 12;
        int n   = (fi >> 1) * 16 + (fi & 1) * 8 + (l >> 2);
        int k   = kk * 8 + (l & 3) + reg * 4;
        int gate = n >> 4, unit = hu0 + (n & 15);
        s_wf[s] = f2tf(Whh[(size_t)(gate * HH + unit) * HH + k]);
    }
    for (int i = tid; i < 512; i += 256) s_c[i] = 0.f;
#pragma unroll
    for (int half = 0; half < 2; half++) {
        int idx = tid + half * 256;
        int b = bg * 32 + (idx >> 4), u = idx & 15;
        hglob[b * HH + hu0 + u] = 0.f;
    }
    gsync_grp(grp);

    const int sl0 = slen[bg * 32 + (tid >> 4)];
    const int sl1 = slen[bg * 32 + 16 + (tid >> 4)];

    const int o0 = g * REC_PAD + tg;
    const int o1 = o0 + 8 * REC_PAD;
    const uint32_t* b0base = s_wf + (wn * 2) * 4096 + lane * 2;
    const uint32_t* b1base = b0base + 4096;

    for (int step = 0; step < LL; ++step) {
        const int t = dir ? (LL - 1 - step) : step;

        // prefetch xg for both halves (consumed after mma)
        float x0[4], x1[4];
        {
            const float* xp0 = xg + ((size_t)t * BB + bg * 32 + (tid >> 4)) * GG + hu0 + (tid & 15);
            x0[0] = xp0[0]; x0[1] = xp0[HH]; x0[2] = xp0[2 * HH]; x0[3] = xp0[3 * HH];
            const float* xp1 = xp0 + 16 * GG;
            x1[0] = xp1[0]; x1[1] = xp1[HH]; x1[2] = xp1[2 * HH]; x1[3] = xp1[3 * HH];
        }

        // stage our 32 h rows -> smem (already tf32; pure copy)
        for (int i = tid; i < 4096; i += 256) {
            int m = i >> 7, kq = (i & 127) << 2;
            float4 v = __ldcg((const float4*)(hsrc + m * HH + kq));
            *(uint4*)(s_h + m * REC_PAD + kq) = *(uint4*)&v;
        }
        __syncthreads();

        float acc0[4] = {0.f, 0.f, 0.f, 0.f};
        float acc1[4] = {0.f, 0.f, 0.f, 0.f};
        const uint32_t* ab = s_h + (wm * 16) * REC_PAD;
#pragma unroll 8
        for (int kk = 0; kk < 64; kk++) {
            const uint32_t* ap = ab + kk * 8;
            uint32_t a[4];
            a[0] = ap[o0];     a[1] = ap[o1];
            a[2] = ap[o0 + 4]; a[3] = ap[o1 + 4];
            uint32_t b0[2], b1[2];
            *(uint2*)b0 = *(const uint2*)(b0base + kk * 64);
            *(uint2*)b1 = *(const uint2*)(b1base + kk * 64);
            mma_tf32(acc0, a, b0);
            mma_tf32(acc1, a, b1);
        }
        {
            int zr = wm * 16 + g;
            int zc = wn * 16 + tg * 2;
            *(float2*)&s_z[zr * ZPAD + zc]           = make_float2(acc0[0], acc0[1]);
            *(float2*)&s_z[(zr + 8) * ZPAD + zc]     = make_float2(acc0[2], acc0[3]);
            *(float2*)&s_z[zr * ZPAD + zc + 8]       = make_float2(acc1[0], acc1[1]);
            *(float2*)&s_z[(zr + 8) * ZPAD + zc + 8] = make_float2(acc1[2], acc1[3]);
        }
        __syncthreads();

        // gates: 2 elements per thread; all nonlinearities on MUFU.TANH
#pragma unroll
        for (int half = 0; half < 2; half++) {
            int idx = tid + half * 256;
            int bl = idx >> 4, u = idx & 15;
            int b = bg * 32 + bl;
            const float* xv = half ? x1 : x0;
            float zi = s_z[bl * ZPAD + u]      + xv[0];
            float zf = s_z[bl * ZPAD + 16 + u] + xv[1];
            float zg = s_z[bl * ZPAD + 32 + u] + xv[2];
            float zo = s_z[bl * ZPAD + 48 + u] + xv[3];
            float c  = s_c[idx];
            float cn = sigm_fast(zf) * c + sigm_fast(zi) * tanha(zg);
            float hn = sigm_fast(zo) * tanha(cn);
            bool act = t < (half ? sl1 : sl0);
            if (act) {
                s_c[idx] = cn;
                hglob[b * HH + hu0 + u] = __uint_as_float(f2tf(hn));  // store tf32 bits
            }
            Hout[(size_t)(b * LL + t) * H2 + dir * HH + hu0 + u] = act ? hn : 0.f;
        }
        gsync_grp(grp);
    }
}

// ---------------- epilogue -----------------------------------------------------
__global__ void k_docsum_part(const float* __restrict__ Hout,
                              const int* __restrict__ dlen, float* __restrict__ part)
{
    int b = blockIdx.x, c = blockIdx.y, tid = threadIdx.x;
    int dl = dlen[b];
    int t0 = c * 32, t1 = min(t0 + 32, dl);
    float acc[4] = {0.f, 0.f, 0.f, 0.f};
    for (int t = t0; t < t1; t++) {
        const float* hp = Hout + (size_t)(b * LL + t) * H2;
#pragma unroll
        for (int j = 0; j < 4; j++) acc[j] += hp[tid + j * 256];
    }
    float* pp = part + ((size_t)c * BB + b) * H2;
#pragma unroll
    for (int j = 0; j < 4; j++) pp[tid + j * 256] = acc[j];
}

__global__ void k_docsum_fin(const float* __restrict__ part,
                             const int* __restrict__ dlen, float* __restrict__ out)
{
    int b = blockIdx.x, tid = threadIdx.x;
    float inv = 1.f / (float)dlen[b];
    float acc[4] = {0.f, 0.f, 0.f, 0.f};
    for (int c = 0; c < 8; c++) {
        const float* pp = part + ((size_t)c * BB + b) * H2;
#pragma unroll
        for (int j = 0; j < 4; j++) acc[j] += pp[tid + j * 256];
    }
#pragma unroll
    for (int j = 0; j < 4; j++) out[b * H2 + tid + j * 256] = acc[j] * inv;
}

__global__ void k_mv(const float* __restrict__ W, const float* __restrict__ v,
                     const float* __restrict__ bias, float* __restrict__ out)
{
    int b = blockIdx.y;
    int wid = threadIdx.x >> 5, lane = threadIdx.x & 31;
    int d = blockIdx.x * 8 + wid;
    const float4* wp = (const float4*)(W + (size_t)d * H2);
    const float4* vp = (const float4*)(v + (size_t)b * H2);
    float acc = 0.f;
    for (int e = lane; e < H2 / 4; e += 32) {
        float4 a = wp[e], c = vp[e];
        acc += a.x * c.x + a.y * c.y + a.z * c.z + a.w * c.w;
    }
#pragma unroll
    for (int off = 16; off > 0; off >>= 1) acc += __shfl_down_sync(0xffffffffu, acc, off);
    if (lane == 0) out[b * H2 + d] = acc + (bias ? bias[d] : 0.f);
}

__global__ void k_base(const float* __restrict__ Hout, const float* __restrict__ S,
                       const float* __restrict__ w_con, const float* __restrict__ b_con,
                       const float* __restrict__ b_sal, const float* __restrict__ pos,
                       float* __restrict__ base)
{
    int b = blockIdx.x;
    int l = blockIdx.y * 8 + (threadIdx.x >> 5);
    int lane = threadIdx.x & 31;
    const float4* hp = (const float4*)(Hout + (size_t)(b * LL + l) * H2);
    const float4* wc = (const float4*)w_con;
    const float4* sp = (const float4*)(S + (size_t)b * H2);
    float a1 = 0.f, a2 = 0.f;
    for (int e = lane; e < H2 / 4; e += 32) {
        float4 h = hp[e], w = wc[e], s = sp[e];
        a1 += h.x * w.x + h.y * w.y + h.z * w.z + h.w * w.w;
        a2 += h.x * s.x + h.y * s.y + h.z * s.z + h.w * s.w;
    }
#pragma unroll
    for (int off = 16; off > 0; off >>= 1) {
        a1 += __shfl_down_sync(0xffffffffu, a1, off);
        a2 += __shfl_down_sync(0xffffffffu, a2, off);
    }
    if (lane == 0) base[b * LL + l] = a1 + a2 + b_con[0] + b_sal[0] + pos[l];
}

__global__ void k_scan(const float* __restrict__ Hout, const float* __restrict__ Hn,
                       const float* __restrict__ base, const float* __restrict__ b_nov,
                       const float* __restrict__ w_cls, const float* __restrict__ b_cls,
                       float* __restrict__ out)
{
    int b = blockIdx.x, lane = threadIdx.x;
    float4 s4[8];
#pragma unroll
    for (int j = 0; j < 8; j++) s4[j] = make_float4(0.f, 0.f, 0.f, 0.f);
    float wcls = w_cls[0], bcls = b_cls[0], bnov = b_nov[0];
    const float4* HnB = (const float4*)(Hn + (size_t)b * LL * H2);
    const float4* HoB = (const float4*)(Hout + (size_t)b * LL * H2);
    for (int i = 0; i < LL; i++) {
        const float4* hn = HnB + (size_t)i * 256 + lane * 8;
        float part = 0.f;
#pragma unroll
        for (int j = 0; j < 8; j++) {
            float4 h = hn[j];
            part += h.x * s4[j].x + h.y * s4[j].y + h.z * s4[j].z + h.w * s4[j].w;
        }
#pragma unroll
        for (int off = 16; off > 0; off >>= 1) part += __shfl_xor_sync(0xffffffffu, part, off);
        float nov = (i == 0) ? 0.f : (part + bnov);
        float p = sigm_fast(wcls * (base[b * LL + i] + nov) + bcls);
        const float4* ho = HoB + (size_t)i * 256 + lane * 8;
#pragma unroll
        for (int j = 0; j < 8; j++) {
            float4 h = ho[j];
            s4[j].x += h.x * p; s4[j].y += h.y * p;
            s4[j].z += h.z * p; s4[j].w += h.w * p;
        }
        if (lane == 0) out[b * LL + i] = p;
    }
}

// ---------------- launch --------------------------------------------------------
extern "C" void kernel_launch(void* const* d_in, const int* in_sizes, int n_in,
                              void* d_out, int out_size)
{
    (void)in_sizes; (void)n_in; (void)out_size;
    const float* x     = (const float*)d_in[0];
    const int*   slen  = (const int*)  d_in[1];
    const int*   dlen  = (const int*)  d_in[2];
    const float* Wih_f = (const float*)d_in[3];
    const float* Whh_f = (const float*)d_in[4];
    const float* b_f   = (const float*)d_in[5];
    const float* Wih_b = (const float*)d_in[6];
    const float* Whh_b = (const float*)d_in[7];
    const float* b_b   = (const float*)d_in[8];
    const float* W_doc = (const float*)d_in[9];
    const float* b_doc = (const float*)d_in[10];
    const float* w_con = (const float*)d_in[11];
    const float* b_con = (const float*)d_in[12];
    const float* W_sal = (const float*)d_in[13];
    const float* b_sal = (const float*)d_in[14];
    const float* W_nov = (const float*)d_in[15];
    const float* b_nov = (const float*)d_in[16];
    const float* pos   = (const float*)d_in[17];
    const float* w_cls = (const float*)d_in[18];
    const float* b_cls = (const float*)d_in[19];
    float* out = (float*)d_out;

    float *p_xg0, *p_xg1, *p_Hout, *p_Hn, *p_WnT, *p_hbuf, *p_part, *p_doc, *p_D, *p_S, *p_base;
    cudaGetSymbolAddress((void**)&p_xg0,  g_xg0);
    cudaGetSymbolAddress((void**)&p_xg1,  g_xg1);
    cudaGetSymbolAddress((void**)&p_Hout, g_Hout);
    cudaGetSymbolAddress((void**)&p_Hn,   g_Hn);
    cudaGetSymbolAddress((void**)&p_WnT,  g_WnT);
    cudaGetSymbolAddress((void**)&p_hbuf, g_hbuf);
    cudaGetSymbolAddress((void**)&p_part, g_docpart);
    cudaGetSymbolAddress((void**)&p_doc,  g_doc);
    cudaGetSymbolAddress((void**)&p_D,    g_D);
    cudaGetSymbolAddress((void**)&p_S,    g_S);
    cudaGetSymbolAddress((void**)&p_base, g_base);

    const int M = BB * LL;

    k_gemm_tf32<true><<<dim3(GG / 128, M / 128), 256>>>(x, Wih_f, b_f, p_xg0, M, GG, EE);
    k_gemm_tf32<true><<<dim3(GG / 128, M / 128), 256>>>(x, Wih_b, b_b, p_xg1, M, GG, EE);
    k_transpose<<<dim3(32, 32), dim3(32, 8)>>>(W_nov, p_WnT);

    const int REC_SMEM = (32 * REC_PAD + 32768 + 32 * ZPAD + 512) * 4;
    cudaFuncSetAttribute(k_recurrent, cudaFuncAttributeMaxDynamicSharedMemorySize, REC_SMEM);
    k_recurrent<<<128, 256, REC_SMEM>>>(Whh_f, Whh_b, slen, p_xg0, p_xg1, p_hbuf, p_Hout);

    k_docsum_part<<<dim3(BB, 8), 256>>>(p_Hout, dlen, p_part);
    k_docsum_fin<<<BB, 256>>>(p_part, dlen, p_doc);
    k_mv<<<dim3(H2 / 8, BB), 256>>>(W_doc, p_doc, b_doc, p_D);
    k_mv<<<dim3(H2 / 8, BB), 256>>>(W_sal, p_D, nullptr, p_S);

    k_gemm_tf32<false><<<dim3(H2 / 128, M / 128), 256>>>(p_Hout, p_WnT, nullptr, p_Hn, M, H2, H2);

    k_base<<<dim3(BB, LL / 8), 256>>>(p_Hout, p_S, w_con, b_con, b_sal, pos, p_base);
    k_scan<<<BB, 32>>>(p_Hout, p_Hn, p_base, b_nov, w_cls, b_cls, out);
}